// round 1
// baseline (speedup 1.0000x reference)
#include <cuda_runtime.h>
#include <math.h>

#define BATCH 4
#define SEQ   2048
#define DMODEL 1024
#define NHEADS 16
#define DK    64
#define DFF   4096
#define NTOK  (BATCH*SEQ)          // 8192

// ---------------- scratch (device globals; no allocation allowed) ----------
__device__ float g_h  [NTOK*DMODEL];
__device__ float g_q  [NTOK*DMODEL];
__device__ float g_k  [NTOK*DMODEL];
__device__ float g_v  [NTOK*DMODEL];
__device__ float g_att[NTOK*DMODEL];
__device__ float g_x1 [NTOK*DMODEL];
__device__ float g_h2 [NTOK*DMODEL];
__device__ float g_ff1[NTOK*DFF];

// ---------------- layernorm: one block per token row ------------------------
__global__ __launch_bounds__(256) void ln_kernel(const float* __restrict__ x,
                                                 const float* __restrict__ g,
                                                 const float* __restrict__ b,
                                                 float* __restrict__ y)
{
    const int row = blockIdx.x;
    const int tid = threadIdx.x;
    const float* xr = x + (size_t)row * DMODEL;
    float4 v = *(const float4*)(xr + tid * 4);
    float s  = v.x + v.y + v.z + v.w;
    float s2 = v.x*v.x + v.y*v.y + v.z*v.z + v.w*v.w;

    __shared__ float red[64], red2[64];
    // warp reduce
    for (int o = 16; o > 0; o >>= 1) {
        s  += __shfl_xor_sync(0xffffffffu, s,  o);
        s2 += __shfl_xor_sync(0xffffffffu, s2, o);
    }
    int wid = tid >> 5, lid = tid & 31;
    if (lid == 0) { red[wid] = s; red2[wid] = s2; }
    __syncthreads();
    if (wid == 0) {
        float a  = (lid < 8) ? red[lid]  : 0.f;
        float a2 = (lid < 8) ? red2[lid] : 0.f;
        for (int o = 4; o > 0; o >>= 1) {
            a  += __shfl_xor_sync(0xffffffffu, a,  o);
            a2 += __shfl_xor_sync(0xffffffffu, a2, o);
        }
        if (lid == 0) { red[0] = a; red2[0] = a2; }
    }
    __syncthreads();
    float mu  = red[0]  * (1.0f / DMODEL);
    float var = red2[0] * (1.0f / DMODEL) - mu * mu;
    float rstd = rsqrtf(var + 1e-5f);

    int c = tid * 4;
    float4 gg = *(const float4*)(g + c);
    float4 bb = *(const float4*)(b + c);
    float4 o;
    o.x = (v.x - mu) * rstd * gg.x + bb.x;
    o.y = (v.y - mu) * rstd * gg.y + bb.y;
    o.z = (v.z - mu) * rstd * gg.z + bb.z;
    o.w = (v.w - mu) * rstd * gg.w + bb.w;
    *(float4*)(y + (size_t)row * DMODEL + c) = o;
}

// ---------------- SGEMM: C = A[M,K] * B[K,N] + bias (+epilogue) -------------
// BM=BN=128, BK=16, 256 threads, 8x8 per thread.
// EPI: 0 = bias, 1 = bias + exact GELU, 2 = bias + residual add
template<int EPI>
__global__ __launch_bounds__(256, 1)
void gemm128(const float* __restrict__ A, const float* __restrict__ B,
             const float* __restrict__ bias, const float* __restrict__ res,
             float* __restrict__ C, int M, int N, int K)
{
    __shared__ float As[16][132];   // padded: 2-way max conflict on store
    __shared__ float Bs[16][128];

    const int tid = threadIdx.x;
    const int tx = tid & 15;        // N direction
    const int ty = tid >> 4;        // M direction
    const int row0 = blockIdx.y * 128;
    const int col0 = blockIdx.x * 128;

    const int arow = tid >> 1;            // 0..127
    const int acol = (tid & 1) * 8;       // 0 or 8
    const int brow = tid >> 4;            // 0..15
    const int bcol = (tid & 15) * 8;      // 0..120

    const float* Aptr = A + (size_t)(row0 + arow) * K + acol;
    const float* Bptr = B + (size_t)brow * N + col0 + bcol;

    float acc[8][8];
#pragma unroll
    for (int i = 0; i < 8; i++)
#pragma unroll
        for (int j = 0; j < 8; j++) acc[i][j] = 0.f;

    for (int k0 = 0; k0 < K; k0 += 16) {
        float4 a0 = *(const float4*)(Aptr + k0);
        float4 a1 = *(const float4*)(Aptr + k0 + 4);
        float4 b0 = *(const float4*)(Bptr + (size_t)k0 * N);
        float4 b1 = *(const float4*)(Bptr + (size_t)k0 * N + 4);

        As[acol + 0][arow] = a0.x; As[acol + 1][arow] = a0.y;
        As[acol + 2][arow] = a0.z; As[acol + 3][arow] = a0.w;
        As[acol + 4][arow] = a1.x; As[acol + 5][arow] = a1.y;
        As[acol + 6][arow] = a1.z; As[acol + 7][arow] = a1.w;
        *(float4*)&Bs[brow][bcol]     = b0;
        *(float4*)&Bs[brow][bcol + 4] = b1;
        __syncthreads();

#pragma unroll
        for (int k = 0; k < 16; k++) {
            float4 fa0 = *(const float4*)&As[k][ty * 8];
            float4 fa1 = *(const float4*)&As[k][ty * 8 + 4];
            float4 fb0 = *(const float4*)&Bs[k][tx * 8];
            float4 fb1 = *(const float4*)&Bs[k][tx * 8 + 4];
            float ar[8] = {fa0.x, fa0.y, fa0.z, fa0.w, fa1.x, fa1.y, fa1.z, fa1.w};
            float br[8] = {fb0.x, fb0.y, fb0.z, fb0.w, fb1.x, fb1.y, fb1.z, fb1.w};
#pragma unroll
            for (int i = 0; i < 8; i++)
#pragma unroll
                for (int j = 0; j < 8; j++)
                    acc[i][j] = fmaf(ar[i], br[j], acc[i][j]);
        }
        __syncthreads();
    }

#pragma unroll
    for (int i = 0; i < 8; i++) {
        int r = row0 + ty * 8 + i;
#pragma unroll
        for (int j = 0; j < 8; j++) {
            int c = col0 + tx * 8 + j;
            float v = acc[i][j] + bias[c];
            if (EPI == 1) {
                v = 0.5f * v * (1.0f + erff(v * 0.70710678118654752f));
            } else if (EPI == 2) {
                v += res[(size_t)r * N + c];
            }
            C[(size_t)r * N + c] = v;
        }
    }
}

// ---------------- attention: thread-per-query-row streaming -----------------
// grid: (SEQ/128, BATCH*NHEADS), block 128. Q,K,V in [token, dmodel] layout,
// head h occupies columns [h*64, h*64+64).
__global__ __launch_bounds__(128)
void attn_kernel(const float* __restrict__ Q, const float* __restrict__ K,
                 const float* __restrict__ V, const int* __restrict__ mask,
                 float* __restrict__ O)
{
    const int tid = threadIdx.x;
    const int b = blockIdx.y >> 4;
    const int h = blockIdx.y & 15;
    const int qrow = blockIdx.x * 128 + tid;   // seq position in batch b

    __shared__ float Ks[64][64];
    __shared__ float Vs[64][64];
    __shared__ int   Ms[64];

    const size_t base = ((size_t)b * SEQ) * DMODEL + h * DK;

    float q[64];
#pragma unroll
    for (int i = 0; i < 16; i++) {
        float4 t = *(const float4*)(Q + base + (size_t)qrow * DMODEL + i * 4);
        q[i*4+0] = t.x * 0.125f; q[i*4+1] = t.y * 0.125f;
        q[i*4+2] = t.z * 0.125f; q[i*4+3] = t.w * 0.125f;
    }
    float acc[64];
#pragma unroll
    for (int i = 0; i < 64; i++) acc[i] = 0.f;
    float l = 0.f;

    for (int kt = 0; kt < SEQ; kt += 64) {
        __syncthreads();
        // cooperative load of 64x64 K and V tiles (+ mask)
#pragma unroll
        for (int i = 0; i < 8; i++) {
            int j   = tid + i * 128;       // float4 chunk id, 0..1023
            int r   = j >> 4;              // 0..63
            int c4  = (j & 15) * 4;        // 0..60
            size_t gofs = base + (size_t)(kt + r) * DMODEL + c4;
            *(float4*)&Ks[r][c4] = *(const float4*)(K + gofs);
            *(float4*)&Vs[r][c4] = *(const float4*)(V + gofs);
        }
        if (tid < 64) Ms[tid] = mask[b * SEQ + kt + tid];
        __syncthreads();

#pragma unroll 4
        for (int kk = 0; kk < 64; kk++) {
            float s = 0.f;
#pragma unroll
            for (int d = 0; d < 64; d++) s = fmaf(q[d], Ks[kk][d], s);
            float p = (Ms[kk] == 0) ? 0.f : __expf(s);
            l += p;
#pragma unroll
            for (int d = 0; d < 64; d++) acc[d] = fmaf(p, Vs[kk][d], acc[d]);
        }
    }

    float inv = 1.0f / l;
    float* outp = O + base + (size_t)qrow * DMODEL;
#pragma unroll
    for (int i = 0; i < 16; i++) {
        float4 t;
        t.x = acc[i*4+0] * inv; t.y = acc[i*4+1] * inv;
        t.z = acc[i*4+2] * inv; t.w = acc[i*4+3] * inv;
        *(float4*)(outp + i * 4) = t;
    }
}

// ---------------- launcher ---------------------------------------------------
extern "C" void kernel_launch(void* const* d_in, const int* in_sizes, int n_in,
                              void* d_out, int out_size)
{
    const float* x     = (const float*)d_in[0];
    const int*   mask  = (const int*)  d_in[1];
    const float* Wq    = (const float*)d_in[2];
    const float* bq    = (const float*)d_in[3];
    const float* Wk    = (const float*)d_in[4];
    const float* bk    = (const float*)d_in[5];
    const float* Wv    = (const float*)d_in[6];
    const float* bv    = (const float*)d_in[7];
    const float* Wo    = (const float*)d_in[8];
    const float* bo    = (const float*)d_in[9];
    const float* W1    = (const float*)d_in[10];
    const float* b1    = (const float*)d_in[11];
    const float* W2    = (const float*)d_in[12];
    const float* b2    = (const float*)d_in[13];
    const float* ln1g  = (const float*)d_in[14];
    const float* ln1b  = (const float*)d_in[15];
    const float* ln2g  = (const float*)d_in[16];
    const float* ln2b  = (const float*)d_in[17];
    float* out = (float*)d_out;

    float *h, *q, *k, *v, *att, *x1, *h2, *ff1;
    cudaGetSymbolAddress((void**)&h,   g_h);
    cudaGetSymbolAddress((void**)&q,   g_q);
    cudaGetSymbolAddress((void**)&k,   g_k);
    cudaGetSymbolAddress((void**)&v,   g_v);
    cudaGetSymbolAddress((void**)&att, g_att);
    cudaGetSymbolAddress((void**)&x1,  g_x1);
    cudaGetSymbolAddress((void**)&h2,  g_h2);
    cudaGetSymbolAddress((void**)&ff1, g_ff1);

    dim3 blk(256);
    dim3 gD(DMODEL / 128, NTOK / 128);   // (8, 64)
    dim3 gF(DFF / 128,    NTOK / 128);   // (32, 64)

    // h = LN1(x)
    ln_kernel<<<NTOK, 256>>>(x, ln1g, ln1b, h);
    // Q,K,V projections
    gemm128<0><<<gD, blk>>>(h, Wq, bq, nullptr, q, NTOK, DMODEL, DMODEL);
    gemm128<0><<<gD, blk>>>(h, Wk, bk, nullptr, k, NTOK, DMODEL, DMODEL);
    gemm128<0><<<gD, blk>>>(h, Wv, bv, nullptr, v, NTOK, DMODEL, DMODEL);
    // attention
    attn_kernel<<<dim3(SEQ / 128, BATCH * NHEADS), 128>>>(q, k, v, mask, att);
    // x1 = x + att @ Wo + bo
    gemm128<2><<<gD, blk>>>(att, Wo, bo, x, x1, NTOK, DMODEL, DMODEL);
    // h2 = LN2(x1)
    ln_kernel<<<NTOK, 256>>>(x1, ln2g, ln2b, h2);
    // ff1 = gelu(h2 @ W1 + b1)
    gemm128<1><<<gF, blk>>>(h2, W1, b1, nullptr, ff1, NTOK, DFF, DMODEL);
    // out = x1 + ff1 @ W2 + b2
    gemm128<2><<<gD, blk>>>(ff1, W2, b2, x1, out, NTOK, DMODEL, DFF);
}

// round 4
// speedup vs baseline: 1.9581x; 1.9581x over previous
#include <cuda_runtime.h>
#include <math.h>
#include <stdint.h>

#define BATCH 4
#define SEQ   2048
#define DMODEL 1024
#define NHEADS 16
#define DK    64
#define DFF   4096
#define NTOK  (BATCH*SEQ)          // 8192

// ---------------- scratch (device globals; no allocation allowed) ----------
__device__ float g_h  [NTOK*DMODEL];
__device__ float g_q  [NTOK*DMODEL];
__device__ float g_k  [NTOK*DMODEL];
__device__ float g_v  [NTOK*DMODEL];
__device__ float g_att[NTOK*DMODEL];
__device__ float g_x1 [NTOK*DMODEL];
__device__ float g_h2 [NTOK*DMODEL];
__device__ float g_ff1[NTOK*DFF];
// transposed (K-major, tf32-rounded) weights
__device__ float g_wqt[DMODEL*DMODEL];
__device__ float g_wkt[DMODEL*DMODEL];
__device__ float g_wvt[DMODEL*DMODEL];
__device__ float g_wot[DMODEL*DMODEL];
__device__ float g_w1t[DFF*DMODEL];     // [N=DFF, K=DMODEL]
__device__ float g_w2t[DMODEL*DFF];     // [N=DMODEL, K=DFF]

// ---------------- helpers ----------------------------------------------------
__device__ __forceinline__ uint32_t smem_u32(const void* p) {
    uint32_t a;
    asm("{ .reg .u64 t; cvta.to.shared.u64 t, %1; cvt.u32.u64 %0, t; }"
        : "=r"(a) : "l"(p));
    return a;
}
__device__ __forceinline__ float rna_tf32(float v) {
    uint32_t u;
    asm("cvt.rna.tf32.f32 %0, %1;" : "=r"(u) : "f"(v));
    return __uint_as_float(u);
}
__device__ __forceinline__ void cp_async16(uint32_t dst, const void* src) {
    asm volatile("cp.async.cg.shared.global [%0], [%1], 16;" :: "r"(dst), "l"(src));
}

__device__ __forceinline__ void mma_tf32(float (&d)[4], const uint32_t (&a)[4],
                                         const uint32_t (&b)[2]) {
    asm volatile("mma.sync.aligned.m16n8k8.row.col.f32.tf32.tf32.f32 "
        "{%0,%1,%2,%3}, {%4,%5,%6,%7}, {%8,%9}, {%0,%1,%2,%3};"
        : "+f"(d[0]), "+f"(d[1]), "+f"(d[2]), "+f"(d[3])
        : "r"(a[0]), "r"(a[1]), "r"(a[2]), "r"(a[3]), "r"(b[0]), "r"(b[1]));
}

// ---------------- layernorm: one block per token row (tf32-rounded out) -----
__global__ __launch_bounds__(256) void ln_kernel(const float* __restrict__ x,
                                                 const float* __restrict__ g,
                                                 const float* __restrict__ b,
                                                 float* __restrict__ y)
{
    const int row = blockIdx.x;
    const int tid = threadIdx.x;
    const float* xr = x + (size_t)row * DMODEL;
    float4 v = *(const float4*)(xr + tid * 4);
    float s  = v.x + v.y + v.z + v.w;
    float s2 = v.x*v.x + v.y*v.y + v.z*v.z + v.w*v.w;

    __shared__ float red[64], red2[64];
    for (int o = 16; o > 0; o >>= 1) {
        s  += __shfl_xor_sync(0xffffffffu, s,  o);
        s2 += __shfl_xor_sync(0xffffffffu, s2, o);
    }
    int wid = tid >> 5, lid = tid & 31;
    if (lid == 0) { red[wid] = s; red2[wid] = s2; }
    __syncthreads();
    if (wid == 0) {
        float a  = (lid < 8) ? red[lid]  : 0.f;
        float a2 = (lid < 8) ? red2[lid] : 0.f;
        for (int o = 4; o > 0; o >>= 1) {
            a  += __shfl_xor_sync(0xffffffffu, a,  o);
            a2 += __shfl_xor_sync(0xffffffffu, a2, o);
        }
        if (lid == 0) { red[0] = a; red2[0] = a2; }
    }
    __syncthreads();
    float mu  = red[0]  * (1.0f / DMODEL);
    float var = red2[0] * (1.0f / DMODEL) - mu * mu;
    float rstd = rsqrtf(var + 1e-5f);

    int c = tid * 4;
    float4 gg = *(const float4*)(g + c);
    float4 bb = *(const float4*)(b + c);
    float4 o;
    o.x = rna_tf32((v.x - mu) * rstd * gg.x + bb.x);
    o.y = rna_tf32((v.y - mu) * rstd * gg.y + bb.y);
    o.z = rna_tf32((v.z - mu) * rstd * gg.z + bb.z);
    o.w = rna_tf32((v.w - mu) * rstd * gg.w + bb.w);
    *(float4*)(y + (size_t)row * DMODEL + c) = o;
}

// ---------------- weight transpose + tf32 round: Wt[n,k] = rna(W[k,n]) ------
__global__ __launch_bounds__(256) void tp_rna(const float* __restrict__ W,
                                              float* __restrict__ Wt, int K, int N)
{
    __shared__ float t[32][33];
    int n0 = blockIdx.x * 32, k0 = blockIdx.y * 32;
    int tx = threadIdx.x, ty = threadIdx.y;  // 32 x 8
#pragma unroll
    for (int i = 0; i < 4; i++)
        t[ty + i*8][tx] = W[(size_t)(k0 + ty + i*8) * N + n0 + tx];
    __syncthreads();
#pragma unroll
    for (int i = 0; i < 4; i++)
        Wt[(size_t)(n0 + ty + i*8) * K + k0 + tx] = rna_tf32(t[tx][ty + i*8]);
}

// ---------------- tf32 mma.sync GEMM: C[M,N] = A[M,K] @ Bt[N,K]^T -----------
// 128x128 tile, BK=32, 256 threads (8 warps, warp tile 64x32), 2-stage cp.async.
// EPI: 0 = bias, 1 = bias + gelu + tf32-round, 2 = bias + residual
#define SST 36                 // smem row stride (floats): 144B, 16B-aligned, 4 mod 32 banks
#define STAGE_F (128*SST)

template<int EPI>
__global__ __launch_bounds__(256)
void gemm_mma(const float* __restrict__ A, const float* __restrict__ Bt,
              const float* __restrict__ bias, const float* __restrict__ res,
              float* __restrict__ C, int M, int N, int K)
{
    extern __shared__ float smf[];
    float* As = smf;                    // [2][128][SST]
    float* Bs = smf + 2 * STAGE_F;
    const int tid = threadIdx.x, lane = tid & 31, w = tid >> 5;
    const int wm = w & 1, wn = w >> 1;          // 2 warps M, 4 warps N
    const int gid = lane >> 2, tig = lane & 3;
    const int row0 = blockIdx.y * 128, col0 = blockIdx.x * 128;

    const uint32_t asb = smem_u32(As), bsb = smem_u32(Bs);

    float acc[4][4][4];
#pragma unroll
    for (int i = 0; i < 4; i++)
#pragma unroll
        for (int j = 0; j < 4; j++)
#pragma unroll
            for (int e = 0; e < 4; e++) acc[i][j][e] = 0.f;

    const int NCH = K >> 5;

    // prologue load of stage 0
    {
#pragma unroll
        for (int it = 0; it < 4; it++) {
            int cchunk = tid + it * 256;        // 0..1023
            int r = cchunk >> 3, j = cchunk & 7;
            uint32_t d = (uint32_t)((r * SST + j * 4) * 4);
            cp_async16(asb + d, A  + (size_t)(row0 + r) * K + j * 4);
            cp_async16(bsb + d, Bt + (size_t)(col0 + r) * K + j * 4);
        }
        asm volatile("cp.async.commit_group;" ::: "memory");
    }

    for (int i = 0; i < NCH; i++) {
        const int buf = i & 1;
        if (i + 1 < NCH) {
            const int nb = buf ^ 1;
            const int kof = (i + 1) << 5;
#pragma unroll
            for (int it = 0; it < 4; it++) {
                int cchunk = tid + it * 256;
                int r = cchunk >> 3, j = cchunk & 7;
                uint32_t d = (uint32_t)((nb * STAGE_F + r * SST + j * 4) * 4);
                cp_async16(asb + d, A  + (size_t)(row0 + r) * K + kof + j * 4);
                cp_async16(bsb + d, Bt + (size_t)(col0 + r) * K + kof + j * 4);
            }
            asm volatile("cp.async.commit_group;" ::: "memory");
            asm volatile("cp.async.wait_group 1;" ::: "memory");
        } else {
            asm volatile("cp.async.wait_group 0;" ::: "memory");
        }
        __syncthreads();

        const float* as = As + buf * STAGE_F;
        const float* bs = Bs + buf * STAGE_F;
#pragma unroll
        for (int ks = 0; ks < 4; ks++) {
            const int k0 = ks * 8 + tig;
            uint32_t af[4][4], bf[4][2];
#pragma unroll
            for (int mt = 0; mt < 4; mt++) {
                int r = wm * 64 + mt * 16 + gid;
                af[mt][0] = __float_as_uint(as[r * SST + k0]);
                af[mt][1] = __float_as_uint(as[(r + 8) * SST + k0]);
                af[mt][2] = __float_as_uint(as[r * SST + k0 + 4]);
                af[mt][3] = __float_as_uint(as[(r + 8) * SST + k0 + 4]);
            }
#pragma unroll
            for (int nt = 0; nt < 4; nt++) {
                int n = wn * 32 + nt * 8 + gid;
                bf[nt][0] = __float_as_uint(bs[n * SST + k0]);
                bf[nt][1] = __float_as_uint(bs[n * SST + k0 + 4]);
            }
#pragma unroll
            for (int mt = 0; mt < 4; mt++)
#pragma unroll
                for (int nt = 0; nt < 4; nt++)
                    mma_tf32(acc[mt][nt], af[mt], bf[nt]);
        }
        __syncthreads();
    }

    // epilogue
#pragma unroll
    for (int mt = 0; mt < 4; mt++) {
        const int r0 = row0 + wm * 64 + mt * 16 + gid;
#pragma unroll
        for (int nt = 0; nt < 4; nt++) {
            const int c = col0 + wn * 32 + nt * 8 + 2 * tig;
            const float b0 = bias[c], b1 = bias[c + 1];
            float o00 = acc[mt][nt][0] + b0, o01 = acc[mt][nt][1] + b1;
            float o10 = acc[mt][nt][2] + b0, o11 = acc[mt][nt][3] + b1;
            if (EPI == 1) {
                o00 = rna_tf32(0.5f * o00 * (1.0f + erff(o00 * 0.70710678118654752f)));
                o01 = rna_tf32(0.5f * o01 * (1.0f + erff(o01 * 0.70710678118654752f)));
                o10 = rna_tf32(0.5f * o10 * (1.0f + erff(o10 * 0.70710678118654752f)));
                o11 = rna_tf32(0.5f * o11 * (1.0f + erff(o11 * 0.70710678118654752f)));
            } else if (EPI == 2) {
                const float* rp0 = res + (size_t)r0 * N + c;
                const float* rp1 = res + (size_t)(r0 + 8) * N + c;
                o00 += rp0[0]; o01 += rp0[1];
                o10 += rp1[0]; o11 += rp1[1];
            }
            float2 v0 = make_float2(o00, o01);
            float2 v1 = make_float2(o10, o11);
            *(float2*)(C + (size_t)r0 * N + c)       = v0;
            *(float2*)(C + (size_t)(r0 + 8) * N + c) = v1;
        }
    }
}

// ---------------- attention: thread-per-query-row streaming -----------------
__global__ __launch_bounds__(128)
void attn_kernel(const float* __restrict__ Q, const float* __restrict__ K,
                 const float* __restrict__ V, const int* __restrict__ mask,
                 float* __restrict__ O)
{
    const int tid = threadIdx.x;
    const int b = blockIdx.y >> 4;
    const int h = blockIdx.y & 15;
    const int qrow = blockIdx.x * 128 + tid;

    __shared__ float Ks[64][64];
    __shared__ float Vs[64][64];
    __shared__ int   Ms[64];

    const size_t base = ((size_t)b * SEQ) * DMODEL + h * DK;

    float q[64];
#pragma unroll
    for (int i = 0; i < 16; i++) {
        float4 t = *(const float4*)(Q + base + (size_t)qrow * DMODEL + i * 4);
        q[i*4+0] = t.x * 0.125f; q[i*4+1] = t.y * 0.125f;
        q[i*4+2] = t.z * 0.125f; q[i*4+3] = t.w * 0.125f;
    }
    float acc[64];
#pragma unroll
    for (int i = 0; i < 64; i++) acc[i] = 0.f;
    float l = 0.f;

    for (int kt = 0; kt < SEQ; kt += 64) {
        __syncthreads();
#pragma unroll
        for (int i = 0; i < 8; i++) {
            int j   = tid + i * 128;
            int r   = j >> 4;
            int c4  = (j & 15) * 4;
            size_t gofs = base + (size_t)(kt + r) * DMODEL + c4;
            *(float4*)&Ks[r][c4] = *(const float4*)(K + gofs);
            *(float4*)&Vs[r][c4] = *(const float4*)(V + gofs);
        }
        if (tid < 64) Ms[tid] = mask[b * SEQ + kt + tid];
        __syncthreads();

#pragma unroll 4
        for (int kk = 0; kk < 64; kk++) {
            float s = 0.f;
#pragma unroll
            for (int d = 0; d < 64; d++) s = fmaf(q[d], Ks[kk][d], s);
            float p = (Ms[kk] == 0) ? 0.f : __expf(s);
            l += p;
#pragma unroll
            for (int d = 0; d < 64; d++) acc[d] = fmaf(p, Vs[kk][d], acc[d]);
        }
    }

    float inv = 1.0f / l;
    float* outp = O + base + (size_t)qrow * DMODEL;
#pragma unroll
    for (int i = 0; i < 16; i++) {
        float4 t;
        t.x = rna_tf32(acc[i*4+0] * inv); t.y = rna_tf32(acc[i*4+1] * inv);
        t.z = rna_tf32(acc[i*4+2] * inv); t.w = rna_tf32(acc[i*4+3] * inv);
        *(float4*)(outp + i * 4) = t;
    }
}

// ---------------- launcher ---------------------------------------------------
extern "C" void kernel_launch(void* const* d_in, const int* in_sizes, int n_in,
                              void* d_out, int out_size)
{
    const float* x     = (const float*)d_in[0];
    const int*   mask  = (const int*)  d_in[1];
    const float* Wq    = (const float*)d_in[2];
    const float* bq    = (const float*)d_in[3];
    const float* Wk    = (const float*)d_in[4];
    const float* bk    = (const float*)d_in[5];
    const float* Wv    = (const float*)d_in[6];
    const float* bv    = (const float*)d_in[7];
    const float* Wo    = (const float*)d_in[8];
    const float* bo    = (const float*)d_in[9];
    const float* W1    = (const float*)d_in[10];
    const float* b1    = (const float*)d_in[11];
    const float* W2    = (const float*)d_in[12];
    const float* b2    = (const float*)d_in[13];
    const float* ln1g  = (const float*)d_in[14];
    const float* ln1b  = (const float*)d_in[15];
    const float* ln2g  = (const float*)d_in[16];
    const float* ln2b  = (const float*)d_in[17];
    float* out = (float*)d_out;

    float *h, *q, *k, *v, *att, *x1, *h2, *ff1;
    float *wqt, *wkt, *wvt, *wot, *w1t, *w2t;
    cudaGetSymbolAddress((void**)&h,   g_h);
    cudaGetSymbolAddress((void**)&q,   g_q);
    cudaGetSymbolAddress((void**)&k,   g_k);
    cudaGetSymbolAddress((void**)&v,   g_v);
    cudaGetSymbolAddress((void**)&att, g_att);
    cudaGetSymbolAddress((void**)&x1,  g_x1);
    cudaGetSymbolAddress((void**)&h2,  g_h2);
    cudaGetSymbolAddress((void**)&ff1, g_ff1);
    cudaGetSymbolAddress((void**)&wqt, g_wqt);
    cudaGetSymbolAddress((void**)&wkt, g_wkt);
    cudaGetSymbolAddress((void**)&wvt, g_wvt);
    cudaGetSymbolAddress((void**)&wot, g_wot);
    cudaGetSymbolAddress((void**)&w1t, g_w1t);
    cudaGetSymbolAddress((void**)&w2t, g_w2t);

    const int SMEM_GEMM = 4 * STAGE_F * sizeof(float);   // 73728 B
    cudaFuncSetAttribute(gemm_mma<0>, cudaFuncAttributeMaxDynamicSharedMemorySize, SMEM_GEMM);
    cudaFuncSetAttribute(gemm_mma<1>, cudaFuncAttributeMaxDynamicSharedMemorySize, SMEM_GEMM);
    cudaFuncSetAttribute(gemm_mma<2>, cudaFuncAttributeMaxDynamicSharedMemorySize, SMEM_GEMM);

    dim3 tpb(32, 8);
    // weight transposes (+tf32 rounding)
    tp_rna<<<dim3(DMODEL/32, DMODEL/32), tpb>>>(Wq, wqt, DMODEL, DMODEL);
    tp_rna<<<dim3(DMODEL/32, DMODEL/32), tpb>>>(Wk, wkt, DMODEL, DMODEL);
    tp_rna<<<dim3(DMODEL/32, DMODEL/32), tpb>>>(Wv, wvt, DMODEL, DMODEL);
    tp_rna<<<dim3(DMODEL/32, DMODEL/32), tpb>>>(Wo, wot, DMODEL, DMODEL);
    tp_rna<<<dim3(DFF/32,    DMODEL/32), tpb>>>(W1, w1t, DMODEL, DFF);
    tp_rna<<<dim3(DMODEL/32, DFF/32),    tpb>>>(W2, w2t, DFF, DMODEL);

    dim3 gD(DMODEL / 128, NTOK / 128);   // (8, 64)
    dim3 gF(DFF / 128,    NTOK / 128);   // (32, 64)

    // h = LN1(x)  (tf32-rounded)
    ln_kernel<<<NTOK, 256>>>(x, ln1g, ln1b, h);
    // Q,K,V projections (tensor core, tf32 mma.sync)
    gemm_mma<0><<<gD, 256, SMEM_GEMM>>>(h, wqt, bq, nullptr, q, NTOK, DMODEL, DMODEL);
    gemm_mma<0><<<gD, 256, SMEM_GEMM>>>(h, wkt, bk, nullptr, k, NTOK, DMODEL, DMODEL);
    gemm_mma<0><<<gD, 256, SMEM_GEMM>>>(h, wvt, bv, nullptr, v, NTOK, DMODEL, DMODEL);
    // attention
    attn_kernel<<<dim3(SEQ / 128, BATCH * NHEADS), 128>>>(q, k, v, mask, att);
    // x1 = x + att @ Wo + bo
    gemm_mma<2><<<gD, 256, SMEM_GEMM>>>(att, wot, bo, x, x1, NTOK, DMODEL, DMODEL);
    // h2 = LN2(x1)  (tf32-rounded)
    ln_kernel<<<NTOK, 256>>>(x1, ln2g, ln2b, h2);
    // ff1 = gelu(h2 @ W1 + b1)  (tf32-rounded)
    gemm_mma<1><<<gF, 256, SMEM_GEMM>>>(h2, w1t, b1, nullptr, ff1, NTOK, DFF, DMODEL);
    // out = x1 + ff1 @ W2 + b2
    gemm_mma<2><<<gD, 256, SMEM_GEMM>>>(ff1, w2t, b2, x1, out, NTOK, DMODEL, DFF);
}

// round 5
// speedup vs baseline: 3.5590x; 1.8176x over previous
#include <cuda_runtime.h>
#include <math.h>
#include <stdint.h>

#define BATCH 4
#define SEQ   2048
#define DMODEL 1024
#define NHEADS 16
#define DK    64
#define DFF   4096
#define NTOK  (BATCH*SEQ)          // 8192
#define QKV_STR 3072

// ---------------- scratch (device globals; no allocation allowed) ----------
__device__ float g_h   [NTOK*DMODEL];
__device__ float g_qkv [NTOK*QKV_STR];
__device__ float g_att [NTOK*DMODEL];
__device__ float g_x1  [NTOK*DMODEL];
__device__ float g_h2  [NTOK*DMODEL];
__device__ float g_ff1 [NTOK*DFF];
// transposed (K-major, tf32-rounded) weights
__device__ float g_wqkvt[3*DMODEL*DMODEL];   // [N=3072, K=1024] (q,k,v stacked)
__device__ float g_bqkv [QKV_STR];
__device__ float g_wot[DMODEL*DMODEL];
__device__ float g_w1t[DFF*DMODEL];     // [N=DFF, K=DMODEL]
__device__ float g_w2t[DMODEL*DFF];     // [N=DMODEL, K=DFF]

// ---------------- helpers ----------------------------------------------------
__device__ __forceinline__ uint32_t smem_u32(const void* p) {
    uint32_t a;
    asm("{ .reg .u64 t; cvta.to.shared.u64 t, %1; cvt.u32.u64 %0, t; }"
        : "=r"(a) : "l"(p));
    return a;
}
__device__ __forceinline__ float rna_tf32(float v) {
    uint32_t u;
    asm("cvt.rna.tf32.f32 %0, %1;" : "=r"(u) : "f"(v));
    return __uint_as_float(u);
}
__device__ __forceinline__ void cp_async16(uint32_t dst, const void* src) {
    asm volatile("cp.async.cg.shared.global [%0], [%1], 16;" :: "r"(dst), "l"(src));
}

__device__ __forceinline__ void mma_tf32(float (&d)[4], const uint32_t (&a)[4],
                                         const uint32_t (&b)[2]) {
    asm volatile("mma.sync.aligned.m16n8k8.row.col.f32.tf32.tf32.f32 "
        "{%0,%1,%2,%3}, {%4,%5,%6,%7}, {%8,%9}, {%0,%1,%2,%3};"
        : "+f"(d[0]), "+f"(d[1]), "+f"(d[2]), "+f"(d[3])
        : "r"(a[0]), "r"(a[1]), "r"(a[2]), "r"(a[3]), "r"(b[0]), "r"(b[1]));
}

// ---------------- layernorm: one block per token row (tf32-rounded out) -----
__global__ __launch_bounds__(256) void ln_kernel(const float* __restrict__ x,
                                                 const float* __restrict__ g,
                                                 const float* __restrict__ b,
                                                 float* __restrict__ y)
{
    const int row = blockIdx.x;
    const int tid = threadIdx.x;
    const float* xr = x + (size_t)row * DMODEL;
    float4 v = *(const float4*)(xr + tid * 4);
    float s  = v.x + v.y + v.z + v.w;
    float s2 = v.x*v.x + v.y*v.y + v.z*v.z + v.w*v.w;

    __shared__ float red[64], red2[64];
    for (int o = 16; o > 0; o >>= 1) {
        s  += __shfl_xor_sync(0xffffffffu, s,  o);
        s2 += __shfl_xor_sync(0xffffffffu, s2, o);
    }
    int wid = tid >> 5, lid = tid & 31;
    if (lid == 0) { red[wid] = s; red2[wid] = s2; }
    __syncthreads();
    if (wid == 0) {
        float a  = (lid < 8) ? red[lid]  : 0.f;
        float a2 = (lid < 8) ? red2[lid] : 0.f;
        for (int o = 4; o > 0; o >>= 1) {
            a  += __shfl_xor_sync(0xffffffffu, a,  o);
            a2 += __shfl_xor_sync(0xffffffffu, a2, o);
        }
        if (lid == 0) { red[0] = a; red2[0] = a2; }
    }
    __syncthreads();
    float mu  = red[0]  * (1.0f / DMODEL);
    float var = red2[0] * (1.0f / DMODEL) - mu * mu;
    float rstd = rsqrtf(var + 1e-5f);

    int c = tid * 4;
    float4 gg = *(const float4*)(g + c);
    float4 bb = *(const float4*)(b + c);
    float4 o;
    o.x = rna_tf32((v.x - mu) * rstd * gg.x + bb.x);
    o.y = rna_tf32((v.y - mu) * rstd * gg.y + bb.y);
    o.z = rna_tf32((v.z - mu) * rstd * gg.z + bb.z);
    o.w = rna_tf32((v.w - mu) * rstd * gg.w + bb.w);
    *(float4*)(y + (size_t)row * DMODEL + c) = o;
}

// ---------------- weight transpose + tf32 round: Wt[n,k] = rna(W[k,n]) ------
__global__ __launch_bounds__(256) void tp_rna(const float* __restrict__ W,
                                              float* __restrict__ Wt, int K, int N)
{
    __shared__ float t[32][33];
    int n0 = blockIdx.x * 32, k0 = blockIdx.y * 32;
    int tx = threadIdx.x, ty = threadIdx.y;  // 32 x 8
#pragma unroll
    for (int i = 0; i < 4; i++)
        t[ty + i*8][tx] = W[(size_t)(k0 + ty + i*8) * N + n0 + tx];
    __syncthreads();
#pragma unroll
    for (int i = 0; i < 4; i++)
        Wt[(size_t)(n0 + ty + i*8) * K + k0 + tx] = rna_tf32(t[tx][ty + i*8]);
}

__global__ void bias_cat(const float* bq, const float* bk, const float* bv,
                         float* o)
{
    int i = blockIdx.x * 256 + threadIdx.x;
    o[i] = (i < DMODEL) ? bq[i] : (i < 2*DMODEL) ? bk[i - DMODEL] : bv[i - 2*DMODEL];
}

// ---------------- tf32 mma.sync GEMM: C[M,N] = A[M,K] @ Bt[N,K]^T -----------
// 128x128 tile, BK=32, 256 threads (8 warps, warp tile 64x32), 2-stage cp.async.
// EPI: 0 = bias + tf32-round, 1 = bias + gelu + tf32-round, 2 = bias + residual
#define SST 36
#define STAGE_F (128*SST)

template<int EPI>
__global__ __launch_bounds__(256)
void gemm_mma(const float* __restrict__ A, const float* __restrict__ Bt,
              const float* __restrict__ bias, const float* __restrict__ res,
              float* __restrict__ C, int M, int N, int K)
{
    extern __shared__ float smf[];
    float* As = smf;
    float* Bs = smf + 2 * STAGE_F;
    const int tid = threadIdx.x, lane = tid & 31, w = tid >> 5;
    const int wm = w & 1, wn = w >> 1;
    const int gid = lane >> 2, tig = lane & 3;
    const int row0 = blockIdx.y * 128, col0 = blockIdx.x * 128;

    const uint32_t asb = smem_u32(As), bsb = smem_u32(Bs);

    float acc[4][4][4];
#pragma unroll
    for (int i = 0; i < 4; i++)
#pragma unroll
        for (int j = 0; j < 4; j++)
#pragma unroll
            for (int e = 0; e < 4; e++) acc[i][j][e] = 0.f;

    const int NCH = K >> 5;
    {
#pragma unroll
        for (int it = 0; it < 4; it++) {
            int cchunk = tid + it * 256;
            int r = cchunk >> 3, j = cchunk & 7;
            uint32_t d = (uint32_t)((r * SST + j * 4) * 4);
            cp_async16(asb + d, A  + (size_t)(row0 + r) * K + j * 4);
            cp_async16(bsb + d, Bt + (size_t)(col0 + r) * K + j * 4);
        }
        asm volatile("cp.async.commit_group;" ::: "memory");
    }

    for (int i = 0; i < NCH; i++) {
        const int buf = i & 1;
        if (i + 1 < NCH) {
            const int nb = buf ^ 1;
            const int kof = (i + 1) << 5;
#pragma unroll
            for (int it = 0; it < 4; it++) {
                int cchunk = tid + it * 256;
                int r = cchunk >> 3, j = cchunk & 7;
                uint32_t d = (uint32_t)((nb * STAGE_F + r * SST + j * 4) * 4);
                cp_async16(asb + d, A  + (size_t)(row0 + r) * K + kof + j * 4);
                cp_async16(bsb + d, Bt + (size_t)(col0 + r) * K + kof + j * 4);
            }
            asm volatile("cp.async.commit_group;" ::: "memory");
            asm volatile("cp.async.wait_group 1;" ::: "memory");
        } else {
            asm volatile("cp.async.wait_group 0;" ::: "memory");
        }
        __syncthreads();

        const float* as = As + buf * STAGE_F;
        const float* bs = Bs + buf * STAGE_F;
#pragma unroll
        for (int ks = 0; ks < 4; ks++) {
            const int k0 = ks * 8 + tig;
            uint32_t af[4][4], bf[4][2];
#pragma unroll
            for (int mt = 0; mt < 4; mt++) {
                int r = wm * 64 + mt * 16 + gid;
                af[mt][0] = __float_as_uint(as[r * SST + k0]);
                af[mt][1] = __float_as_uint(as[(r + 8) * SST + k0]);
                af[mt][2] = __float_as_uint(as[r * SST + k0 + 4]);
                af[mt][3] = __float_as_uint(as[(r + 8) * SST + k0 + 4]);
            }
#pragma unroll
            for (int nt = 0; nt < 4; nt++) {
                int n = wn * 32 + nt * 8 + gid;
                bf[nt][0] = __float_as_uint(bs[n * SST + k0]);
                bf[nt][1] = __float_as_uint(bs[n * SST + k0 + 4]);
            }
#pragma unroll
            for (int mt = 0; mt < 4; mt++)
#pragma unroll
                for (int nt = 0; nt < 4; nt++)
                    mma_tf32(acc[mt][nt], af[mt], bf[nt]);
        }
        __syncthreads();
    }

#pragma unroll
    for (int mt = 0; mt < 4; mt++) {
        const int r0 = row0 + wm * 64 + mt * 16 + gid;
#pragma unroll
        for (int nt = 0; nt < 4; nt++) {
            const int c = col0 + wn * 32 + nt * 8 + 2 * tig;
            const float b0 = bias[c], b1 = bias[c + 1];
            float o00 = acc[mt][nt][0] + b0, o01 = acc[mt][nt][1] + b1;
            float o10 = acc[mt][nt][2] + b0, o11 = acc[mt][nt][3] + b1;
            if (EPI == 0) {
                o00 = rna_tf32(o00); o01 = rna_tf32(o01);
                o10 = rna_tf32(o10); o11 = rna_tf32(o11);
            } else if (EPI == 1) {
                o00 = rna_tf32(0.5f * o00 * (1.0f + erff(o00 * 0.70710678118654752f)));
                o01 = rna_tf32(0.5f * o01 * (1.0f + erff(o01 * 0.70710678118654752f)));
                o10 = rna_tf32(0.5f * o10 * (1.0f + erff(o10 * 0.70710678118654752f)));
                o11 = rna_tf32(0.5f * o11 * (1.0f + erff(o11 * 0.70710678118654752f)));
            } else if (EPI == 2) {
                const float* rp0 = res + (size_t)r0 * N + c;
                const float* rp1 = res + (size_t)(r0 + 8) * N + c;
                o00 += rp0[0]; o01 += rp0[1];
                o10 += rp1[0]; o11 += rp1[1];
            }
            *(float2*)(C + (size_t)r0 * N + c)       = make_float2(o00, o01);
            *(float2*)(C + (size_t)(r0 + 8) * N + c) = make_float2(o10, o11);
        }
    }
}

// ---------------- attention: tf32 mma.sync flash-style ----------------------
// block = (b,h) x 128 q-rows; 256 threads = 8 warps x 16 q-rows.
// K/V tiles of 64 tokens, double-buffered cp.async.
#define KPAD 68
#define VPAD 72
#define KS_F (64*KPAD)
#define VS_F (64*VPAD)
#define PS_F (128*KPAD)
#define ATT_SMEM ((2*KS_F + 2*VS_F + PS_F)*4 + 2*64*4)   // 107008 B

__global__ __launch_bounds__(256)
void attn_mma(const float* __restrict__ QKV, const int* __restrict__ mask,
              float* __restrict__ O)
{
    extern __shared__ float sm[];
    float* Ks = sm;
    float* Vs = sm + 2 * KS_F;
    float* Ps = Vs + 2 * VS_F;
    int*   Ms = (int*)(Ps + PS_F);

    const int tid = threadIdx.x, lane = tid & 31, w = tid >> 5;
    const int gid = lane >> 2, tig = lane & 3;
    const int b = blockIdx.y >> 4, h = blockIdx.y & 15;
    const int q0 = blockIdx.x * 128, m0 = w * 16;
    const size_t tokbase = (size_t)b * SEQ;
    const int qoff = h * DK, koff = DMODEL + h * DK, voff = 2 * DMODEL + h * DK;

    const uint32_t ksb = smem_u32(Ks), vsb = smem_u32(Vs), msb = smem_u32(Ms);

    // ---- stage Q (scaled by 1/8) into Ps, then register fragments ----
#pragma unroll
    for (int i = 0; i < 8; i++) {
        int idx = tid + i * 256;            // 0..2047 float4 chunks
        int r = idx >> 4, j = (idx & 15) * 4;
        float4 t = *(const float4*)(QKV + (tokbase + q0 + r) * QKV_STR + qoff + j);
        t.x *= 0.125f; t.y *= 0.125f; t.z *= 0.125f; t.w *= 0.125f;
        *(float4*)(Ps + r * KPAD + j) = t;
    }
    __syncthreads();
    uint32_t qf[8][4];
#pragma unroll
    for (int ks = 0; ks < 8; ks++) {
        qf[ks][0] = __float_as_uint(Ps[(m0 + gid)     * KPAD + ks * 8 + tig]);
        qf[ks][1] = __float_as_uint(Ps[(m0 + gid + 8) * KPAD + ks * 8 + tig]);
        qf[ks][2] = __float_as_uint(Ps[(m0 + gid)     * KPAD + ks * 8 + tig + 4]);
        qf[ks][3] = __float_as_uint(Ps[(m0 + gid + 8) * KPAD + ks * 8 + tig + 4]);
    }
    __syncthreads();

    float o[8][4];
#pragma unroll
    for (int a = 0; a < 8; a++)
#pragma unroll
        for (int e = 0; e < 4; e++) o[a][e] = 0.f;
    float l0 = 0.f, l1 = 0.f;

    // prologue: load tile 0 into buf 0
    {
#pragma unroll
        for (int i = 0; i < 4; i++) {
            int idx = tid + i * 256;
            int r = idx >> 4, j = (idx & 15) * 4;
            const float* src = QKV + (tokbase + r) * QKV_STR;
            cp_async16(ksb + (uint32_t)((r * KPAD + j) * 4), src + koff + j);
            cp_async16(vsb + (uint32_t)((r * VPAD + j) * 4), src + voff + j);
        }
        if (tid < 16) cp_async16(msb + tid * 16, mask + b * SEQ + tid * 4);
        asm volatile("cp.async.commit_group;" ::: "memory");
    }

    const int NT = SEQ / 64;
    for (int kt = 0; kt < NT; kt++) {
        const int buf = kt & 1;
        if (kt + 1 < NT) {
            const int nb = buf ^ 1;
            const int t0 = (kt + 1) * 64;
#pragma unroll
            for (int i = 0; i < 4; i++) {
                int idx = tid + i * 256;
                int r = idx >> 4, j = (idx & 15) * 4;
                const float* src = QKV + (tokbase + t0 + r) * QKV_STR;
                cp_async16(ksb + (uint32_t)((nb * KS_F + r * KPAD + j) * 4), src + koff + j);
                cp_async16(vsb + (uint32_t)((nb * VS_F + r * VPAD + j) * 4), src + voff + j);
            }
            if (tid < 16) cp_async16(msb + nb * 256 + tid * 16, mask + b * SEQ + t0 + tid * 4);
            asm volatile("cp.async.commit_group;" ::: "memory");
            asm volatile("cp.async.wait_group 1;" ::: "memory");
        } else {
            asm volatile("cp.async.wait_group 0;" ::: "memory");
        }
        __syncthreads();

        const float* ks_ = Ks + buf * KS_F;
        const float* vs_ = Vs + buf * VS_F;
        const int*   ms_ = Ms + buf * 64;

        // S = Q K^T, then P = exp(S) into Ps
#pragma unroll
        for (int at = 0; at < 8; at++) {
            float s[4] = {0.f, 0.f, 0.f, 0.f};
#pragma unroll
            for (int ks = 0; ks < 8; ks++) {
                uint32_t bf[2];
                bf[0] = __float_as_uint(ks_[(at * 8 + gid) * KPAD + ks * 8 + tig]);
                bf[1] = __float_as_uint(ks_[(at * 8 + gid) * KPAD + ks * 8 + tig + 4]);
                mma_tf32(s, qf[ks], bf);
            }
            const int c0 = at * 8 + 2 * tig;
            const int mk0 = ms_[c0], mk1 = ms_[c0 + 1];
            float p0 = mk0 ? rna_tf32(__expf(s[0])) : 0.f;
            float p1 = mk1 ? rna_tf32(__expf(s[1])) : 0.f;
            float p2 = mk0 ? rna_tf32(__expf(s[2])) : 0.f;
            float p3 = mk1 ? rna_tf32(__expf(s[3])) : 0.f;
            l0 += p0 + p1;
            l1 += p2 + p3;
            *(float2*)(Ps + (m0 + gid)     * KPAD + c0) = make_float2(p0, p1);
            *(float2*)(Ps + (m0 + gid + 8) * KPAD + c0) = make_float2(p2, p3);
        }
        __syncwarp();

        // O += P V
#pragma unroll
        for (int ks = 0; ks < 8; ks++) {
            uint32_t af[4];
            af[0] = __float_as_uint(Ps[(m0 + gid)     * KPAD + ks * 8 + tig]);
            af[1] = __float_as_uint(Ps[(m0 + gid + 8) * KPAD + ks * 8 + tig]);
            af[2] = __float_as_uint(Ps[(m0 + gid)     * KPAD + ks * 8 + tig + 4]);
            af[3] = __float_as_uint(Ps[(m0 + gid + 8) * KPAD + ks * 8 + tig + 4]);
#pragma unroll
            for (int at = 0; at < 8; at++) {
                uint32_t bf[2];
                bf[0] = __float_as_uint(vs_[(ks * 8 + tig)     * VPAD + at * 8 + gid]);
                bf[1] = __float_as_uint(vs_[(ks * 8 + tig + 4) * VPAD + at * 8 + gid]);
                mma_tf32(o[at], af, bf);
            }
        }
        __syncthreads();   // all warps done with this buf before it is reloaded
    }

    // row sums across quad
    l0 += __shfl_xor_sync(0xffffffffu, l0, 1);
    l0 += __shfl_xor_sync(0xffffffffu, l0, 2);
    l1 += __shfl_xor_sync(0xffffffffu, l1, 1);
    l1 += __shfl_xor_sync(0xffffffffu, l1, 2);
    const float inv0 = 1.0f / l0, inv1 = 1.0f / l1;

    float* o0 = O + (tokbase + q0 + m0 + gid)     * DMODEL + h * DK;
    float* o1 = O + (tokbase + q0 + m0 + gid + 8) * DMODEL + h * DK;
#pragma unroll
    for (int at = 0; at < 8; at++) {
        const int c = at * 8 + 2 * tig;
        *(float2*)(o0 + c) = make_float2(rna_tf32(o[at][0] * inv0),
                                         rna_tf32(o[at][1] * inv0));
        *(float2*)(o1 + c) = make_float2(rna_tf32(o[at][2] * inv1),
                                         rna_tf32(o[at][3] * inv1));
    }
}

// ---------------- launcher ---------------------------------------------------
extern "C" void kernel_launch(void* const* d_in, const int* in_sizes, int n_in,
                              void* d_out, int out_size)
{
    const float* x     = (const float*)d_in[0];
    const int*   mask  = (const int*)  d_in[1];
    const float* Wq    = (const float*)d_in[2];
    const float* bq    = (const float*)d_in[3];
    const float* Wk    = (const float*)d_in[4];
    const float* bk    = (const float*)d_in[5];
    const float* Wv    = (const float*)d_in[6];
    const float* bv    = (const float*)d_in[7];
    const float* Wo    = (const float*)d_in[8];
    const float* bo    = (const float*)d_in[9];
    const float* W1    = (const float*)d_in[10];
    const float* b1    = (const float*)d_in[11];
    const float* W2    = (const float*)d_in[12];
    const float* b2    = (const float*)d_in[13];
    const float* ln1g  = (const float*)d_in[14];
    const float* ln1b  = (const float*)d_in[15];
    const float* ln2g  = (const float*)d_in[16];
    const float* ln2b  = (const float*)d_in[17];
    float* out = (float*)d_out;

    float *h, *qkv, *att, *x1, *h2, *ff1;
    float *wqkvt, *bqkv, *wot, *w1t, *w2t;
    cudaGetSymbolAddress((void**)&h,    g_h);
    cudaGetSymbolAddress((void**)&qkv,  g_qkv);
    cudaGetSymbolAddress((void**)&att,  g_att);
    cudaGetSymbolAddress((void**)&x1,   g_x1);
    cudaGetSymbolAddress((void**)&h2,   g_h2);
    cudaGetSymbolAddress((void**)&ff1,  g_ff1);
    cudaGetSymbolAddress((void**)&wqkvt,g_wqkvt);
    cudaGetSymbolAddress((void**)&bqkv, g_bqkv);
    cudaGetSymbolAddress((void**)&wot,  g_wot);
    cudaGetSymbolAddress((void**)&w1t,  g_w1t);
    cudaGetSymbolAddress((void**)&w2t,  g_w2t);

    const int SMEM_GEMM = 4 * STAGE_F * sizeof(float);   // 73728 B
    cudaFuncSetAttribute(gemm_mma<0>, cudaFuncAttributeMaxDynamicSharedMemorySize, SMEM_GEMM);
    cudaFuncSetAttribute(gemm_mma<1>, cudaFuncAttributeMaxDynamicSharedMemorySize, SMEM_GEMM);
    cudaFuncSetAttribute(gemm_mma<2>, cudaFuncAttributeMaxDynamicSharedMemorySize, SMEM_GEMM);
    cudaFuncSetAttribute(attn_mma,    cudaFuncAttributeMaxDynamicSharedMemorySize, ATT_SMEM);

    dim3 tpb(32, 8);
    // weight transposes (+tf32 rounding); q,k,v stacked along N
    tp_rna<<<dim3(DMODEL/32, DMODEL/32), tpb>>>(Wq, wqkvt,                 DMODEL, DMODEL);
    tp_rna<<<dim3(DMODEL/32, DMODEL/32), tpb>>>(Wk, wqkvt + DMODEL*DMODEL, DMODEL, DMODEL);
    tp_rna<<<dim3(DMODEL/32, DMODEL/32), tpb>>>(Wv, wqkvt + 2*DMODEL*DMODEL, DMODEL, DMODEL);
    tp_rna<<<dim3(DMODEL/32, DMODEL/32), tpb>>>(Wo, wot, DMODEL, DMODEL);
    tp_rna<<<dim3(DFF/32,    DMODEL/32), tpb>>>(W1, w1t, DMODEL, DFF);
    tp_rna<<<dim3(DMODEL/32, DFF/32),    tpb>>>(W2, w2t, DFF, DMODEL);
    bias_cat<<<QKV_STR/256, 256>>>(bq, bk, bv, bqkv);

    dim3 gD(DMODEL / 128, NTOK / 128);   // (8, 64)
    dim3 gQKV(QKV_STR / 128, NTOK / 128);// (24, 64)
    dim3 gF(DFF / 128,    NTOK / 128);   // (32, 64)

    // h = LN1(x)  (tf32-rounded)
    ln_kernel<<<NTOK, 256>>>(x, ln1g, ln1b, h);
    // fused QKV projection (tf32-rounded outputs: mma operands downstream)
    gemm_mma<0><<<gQKV, 256, SMEM_GEMM>>>(h, wqkvt, bqkv, nullptr, qkv, NTOK, QKV_STR, DMODEL);
    // attention (tensor core)
    attn_mma<<<dim3(SEQ / 128, BATCH * NHEADS), 256, ATT_SMEM>>>(qkv, mask, att);
    // x1 = x + att @ Wo + bo
    gemm_mma<2><<<gD, 256, SMEM_GEMM>>>(att, wot, bo, x, x1, NTOK, DMODEL, DMODEL);
    // h2 = LN2(x1)  (tf32-rounded)
    ln_kernel<<<NTOK, 256>>>(x1, ln2g, ln2b, h2);
    // ff1 = gelu(h2 @ W1 + b1)  (tf32-rounded)
    gemm_mma<1><<<gF, 256, SMEM_GEMM>>>(h2, w1t, b1, nullptr, ff1, NTOK, DFF, DMODEL);
    // out = x1 + ff1 @ W2 + b2
    gemm_mma<2><<<gD, 256, SMEM_GEMM>>>(ff1, w2t, b2, x1, out, NTOK, DMODEL, DFF);
}

// round 6
// speedup vs baseline: 4.2293x; 1.1883x over previous
#include <cuda_runtime.h>
#include <math.h>
#include <stdint.h>

#define BATCH 4
#define SEQ   2048
#define DMODEL 1024
#define NHEADS 16
#define DK    64
#define DFF   4096
#define NTOK  (BATCH*SEQ)          // 8192
#define QKV_STR 3072

// ---------------- scratch (device globals; no allocation allowed) ----------
__device__ float g_h   [NTOK*DMODEL];
__device__ float g_qkv [NTOK*QKV_STR];
__device__ float g_att [NTOK*DMODEL];
__device__ float g_x1  [NTOK*DMODEL];
__device__ float g_h2  [NTOK*DMODEL];
__device__ float g_ff1 [NTOK*DFF];
// transposed (K-major, tf32-rounded) weights
__device__ float g_wqkvt[3*DMODEL*DMODEL];   // [N=3072, K=1024] (q,k,v stacked)
__device__ float g_bqkv [QKV_STR];
__device__ float g_wot[DMODEL*DMODEL];
__device__ float g_w1t[DFF*DMODEL];     // [N=DFF, K=DMODEL]
__device__ float g_w2t[DMODEL*DFF];     // [N=DMODEL, K=DFF]

// ---------------- helpers ----------------------------------------------------
__device__ __forceinline__ uint32_t smem_u32(const void* p) {
    uint32_t a;
    asm("{ .reg .u64 t; cvta.to.shared.u64 t, %1; cvt.u32.u64 %0, t; }"
        : "=r"(a) : "l"(p));
    return a;
}
__device__ __forceinline__ float rna_tf32(float v) {
    uint32_t u;
    asm("cvt.rna.tf32.f32 %0, %1;" : "=r"(u) : "f"(v));
    return __uint_as_float(u);
}
__device__ __forceinline__ void cp_async16(uint32_t dst, const void* src) {
    asm volatile("cp.async.cg.shared.global [%0], [%1], 16;" :: "r"(dst), "l"(src));
}

__device__ __forceinline__ void mma_tf32(float (&d)[4], const uint32_t (&a)[4],
                                         const uint32_t (&b)[2]) {
    asm volatile("mma.sync.aligned.m16n8k8.row.col.f32.tf32.tf32.f32 "
        "{%0,%1,%2,%3}, {%4,%5,%6,%7}, {%8,%9}, {%0,%1,%2,%3};"
        : "+f"(d[0]), "+f"(d[1]), "+f"(d[2]), "+f"(d[3])
        : "r"(a[0]), "r"(a[1]), "r"(a[2]), "r"(a[3]), "r"(b[0]), "r"(b[1]));
}

// ---------------- layernorm: one block per token row (tf32-rounded out) -----
__global__ __launch_bounds__(256) void ln_kernel(const float* __restrict__ x,
                                                 const float* __restrict__ g,
                                                 const float* __restrict__ b,
                                                 float* __restrict__ y)
{
    const int row = blockIdx.x;
    const int tid = threadIdx.x;
    const float* xr = x + (size_t)row * DMODEL;
    float4 v = *(const float4*)(xr + tid * 4);
    float s  = v.x + v.y + v.z + v.w;
    float s2 = v.x*v.x + v.y*v.y + v.z*v.z + v.w*v.w;

    __shared__ float red[64], red2[64];
    for (int o = 16; o > 0; o >>= 1) {
        s  += __shfl_xor_sync(0xffffffffu, s,  o);
        s2 += __shfl_xor_sync(0xffffffffu, s2, o);
    }
    int wid = tid >> 5, lid = tid & 31;
    if (lid == 0) { red[wid] = s; red2[wid] = s2; }
    __syncthreads();
    if (wid == 0) {
        float a  = (lid < 8) ? red[lid]  : 0.f;
        float a2 = (lid < 8) ? red2[lid] : 0.f;
        for (int o = 4; o > 0; o >>= 1) {
            a  += __shfl_xor_sync(0xffffffffu, a,  o);
            a2 += __shfl_xor_sync(0xffffffffu, a2, o);
        }
        if (lid == 0) { red[0] = a; red2[0] = a2; }
    }
    __syncthreads();
    float mu  = red[0]  * (1.0f / DMODEL);
    float var = red2[0] * (1.0f / DMODEL) - mu * mu;
    float rstd = rsqrtf(var + 1e-5f);

    int c = tid * 4;
    float4 gg = *(const float4*)(g + c);
    float4 bb = *(const float4*)(b + c);
    float4 o;
    o.x = rna_tf32((v.x - mu) * rstd * gg.x + bb.x);
    o.y = rna_tf32((v.y - mu) * rstd * gg.y + bb.y);
    o.z = rna_tf32((v.z - mu) * rstd * gg.z + bb.z);
    o.w = rna_tf32((v.w - mu) * rstd * gg.w + bb.w);
    *(float4*)(y + (size_t)row * DMODEL + c) = o;
}

// ---------------- weight transpose + tf32 round: Wt[n,k] = rna(W[k,n]) ------
__global__ __launch_bounds__(256) void tp_rna(const float* __restrict__ W,
                                              float* __restrict__ Wt, int K, int N)
{
    __shared__ float t[32][33];
    int n0 = blockIdx.x * 32, k0 = blockIdx.y * 32;
    int tx = threadIdx.x, ty = threadIdx.y;  // 32 x 8
#pragma unroll
    for (int i = 0; i < 4; i++)
        t[ty + i*8][tx] = W[(size_t)(k0 + ty + i*8) * N + n0 + tx];
    __syncthreads();
#pragma unroll
    for (int i = 0; i < 4; i++)
        Wt[(size_t)(n0 + ty + i*8) * K + k0 + tx] = rna_tf32(t[tx][ty + i*8]);
}

__global__ void bias_cat(const float* bq, const float* bk, const float* bv,
                         float* o)
{
    int i = blockIdx.x * 256 + threadIdx.x;
    o[i] = (i < DMODEL) ? bq[i] : (i < 2*DMODEL) ? bk[i - DMODEL] : bv[i - 2*DMODEL];
}

// ---------------- tf32 mma.sync GEMM: C[M,N] = A[M,K] @ Bt[N,K]^T -----------
// 128x128 tile, BK=32, 256 threads (8 warps, warp tile 64x32), 2-stage cp.async.
// XOR-swizzled smem (stride 32, no padding) -> 64KB total -> 2 CTAs/SM.
// EPI: 0 = bias + tf32-round, 1 = bias + gelu + tf32-round, 2 = bias + residual
#define STAGE_F (128*32)
#define SW(r, c) ((r) * 32 + ((c) ^ (((r) & 7) * 4)))

template<int EPI>
__global__ __launch_bounds__(256, 2)
void gemm_mma(const float* __restrict__ A, const float* __restrict__ Bt,
              const float* __restrict__ bias, const float* __restrict__ res,
              float* __restrict__ C, int M, int N, int K)
{
    extern __shared__ float smf[];
    float* As = smf;
    float* Bs = smf + 2 * STAGE_F;
    const int tid = threadIdx.x, lane = tid & 31, w = tid >> 5;
    const int wm = w & 1, wn = w >> 1;
    const int gid = lane >> 2, tig = lane & 3;
    const int row0 = blockIdx.y * 128, col0 = blockIdx.x * 128;

    const uint32_t asb = smem_u32(As), bsb = smem_u32(Bs);

    float acc[4][4][4];
#pragma unroll
    for (int i = 0; i < 4; i++)
#pragma unroll
        for (int j = 0; j < 4; j++)
#pragma unroll
            for (int e = 0; e < 4; e++) acc[i][j][e] = 0.f;

    const int NCH = K >> 5;
    {
#pragma unroll
        for (int it = 0; it < 4; it++) {
            int cchunk = tid + it * 256;
            int r = cchunk >> 3, j = cchunk & 7;
            uint32_t d = (uint32_t)(SW(r, j * 4) * 4);
            cp_async16(asb + d, A  + (size_t)(row0 + r) * K + j * 4);
            cp_async16(bsb + d, Bt + (size_t)(col0 + r) * K + j * 4);
        }
        asm volatile("cp.async.commit_group;" ::: "memory");
    }

    for (int i = 0; i < NCH; i++) {
        const int buf = i & 1;
        if (i + 1 < NCH) {
            const int nb = buf ^ 1;
            const int kof = (i + 1) << 5;
#pragma unroll
            for (int it = 0; it < 4; it++) {
                int cchunk = tid + it * 256;
                int r = cchunk >> 3, j = cchunk & 7;
                uint32_t d = (uint32_t)((nb * STAGE_F + SW(r, j * 4)) * 4);
                cp_async16(asb + d, A  + (size_t)(row0 + r) * K + kof + j * 4);
                cp_async16(bsb + d, Bt + (size_t)(col0 + r) * K + kof + j * 4);
            }
            asm volatile("cp.async.commit_group;" ::: "memory");
            asm volatile("cp.async.wait_group 1;" ::: "memory");
        } else {
            asm volatile("cp.async.wait_group 0;" ::: "memory");
        }
        __syncthreads();

        const float* as = As + buf * STAGE_F;
        const float* bs = Bs + buf * STAGE_F;
#pragma unroll
        for (int ks = 0; ks < 4; ks++) {
            const int k0 = ks * 8 + tig;
            uint32_t af[4][4], bf[4][2];
#pragma unroll
            for (int mt = 0; mt < 4; mt++) {
                int r = wm * 64 + mt * 16 + gid;
                af[mt][0] = __float_as_uint(as[SW(r, k0)]);
                af[mt][1] = __float_as_uint(as[SW(r + 8, k0)]);
                af[mt][2] = __float_as_uint(as[SW(r, k0 + 4)]);
                af[mt][3] = __float_as_uint(as[SW(r + 8, k0 + 4)]);
            }
#pragma unroll
            for (int nt = 0; nt < 4; nt++) {
                int n = wn * 32 + nt * 8 + gid;
                bf[nt][0] = __float_as_uint(bs[SW(n, k0)]);
                bf[nt][1] = __float_as_uint(bs[SW(n, k0 + 4)]);
            }
#pragma unroll
            for (int mt = 0; mt < 4; mt++)
#pragma unroll
                for (int nt = 0; nt < 4; nt++)
                    mma_tf32(acc[mt][nt], af[mt], bf[nt]);
        }
        __syncthreads();
    }

#pragma unroll
    for (int mt = 0; mt < 4; mt++) {
        const int r0 = row0 + wm * 64 + mt * 16 + gid;
#pragma unroll
        for (int nt = 0; nt < 4; nt++) {
            const int c = col0 + wn * 32 + nt * 8 + 2 * tig;
            const float b0 = bias[c], b1 = bias[c + 1];
            float o00 = acc[mt][nt][0] + b0, o01 = acc[mt][nt][1] + b1;
            float o10 = acc[mt][nt][2] + b0, o11 = acc[mt][nt][3] + b1;
            if (EPI == 0) {
                o00 = rna_tf32(o00); o01 = rna_tf32(o01);
                o10 = rna_tf32(o10); o11 = rna_tf32(o11);
            } else if (EPI == 1) {
                o00 = rna_tf32(0.5f * o00 * (1.0f + erff(o00 * 0.70710678118654752f)));
                o01 = rna_tf32(0.5f * o01 * (1.0f + erff(o01 * 0.70710678118654752f)));
                o10 = rna_tf32(0.5f * o10 * (1.0f + erff(o10 * 0.70710678118654752f)));
                o11 = rna_tf32(0.5f * o11 * (1.0f + erff(o11 * 0.70710678118654752f)));
            } else if (EPI == 2) {
                const float* rp0 = res + (size_t)r0 * N + c;
                const float* rp1 = res + (size_t)(r0 + 8) * N + c;
                o00 += rp0[0]; o01 += rp0[1];
                o10 += rp1[0]; o11 += rp1[1];
            }
            *(float2*)(C + (size_t)r0 * N + c)       = make_float2(o00, o01);
            *(float2*)(C + (size_t)(r0 + 8) * N + c) = make_float2(o10, o11);
        }
    }
}

// ---------------- attention: tf32 mma.sync flash-style ----------------------
// block = (b,h) x 128 q-rows; 256 threads = 8 warps x 16 q-rows.
// K/V tiles of 64 tokens, double-buffered cp.async.
#define KPAD 68
#define VPAD 72
#define KS_F (64*KPAD)
#define VS_F (64*VPAD)
#define PS_F (128*KPAD)
#define ATT_SMEM ((2*KS_F + 2*VS_F + PS_F)*4 + 2*64*4)   // 107008 B

__global__ __launch_bounds__(256, 2)
void attn_mma(const float* __restrict__ QKV, const int* __restrict__ mask,
              float* __restrict__ O)
{
    extern __shared__ float sm[];
    float* Ks = sm;
    float* Vs = sm + 2 * KS_F;
    float* Ps = Vs + 2 * VS_F;
    int*   Ms = (int*)(Ps + PS_F);

    const int tid = threadIdx.x, lane = tid & 31, w = tid >> 5;
    const int gid = lane >> 2, tig = lane & 3;
    const int b = blockIdx.y >> 4, h = blockIdx.y & 15;
    const int q0 = blockIdx.x * 128, m0 = w * 16;
    const size_t tokbase = (size_t)b * SEQ;
    const int qoff = h * DK, koff = DMODEL + h * DK, voff = 2 * DMODEL + h * DK;

    const uint32_t ksb = smem_u32(Ks), vsb = smem_u32(Vs), msb = smem_u32(Ms);

    // ---- stage Q (scaled by 1/8) into Ps, then register fragments ----
#pragma unroll
    for (int i = 0; i < 8; i++) {
        int idx = tid + i * 256;            // 0..2047 float4 chunks
        int r = idx >> 4, j = (idx & 15) * 4;
        float4 t = *(const float4*)(QKV + (tokbase + q0 + r) * QKV_STR + qoff + j);
        t.x *= 0.125f; t.y *= 0.125f; t.z *= 0.125f; t.w *= 0.125f;
        *(float4*)(Ps + r * KPAD + j) = t;
    }
    __syncthreads();
    uint32_t qf[8][4];
#pragma unroll
    for (int ks = 0; ks < 8; ks++) {
        qf[ks][0] = __float_as_uint(Ps[(m0 + gid)     * KPAD + ks * 8 + tig]);
        qf[ks][1] = __float_as_uint(Ps[(m0 + gid + 8) * KPAD + ks * 8 + tig]);
        qf[ks][2] = __float_as_uint(Ps[(m0 + gid)     * KPAD + ks * 8 + tig + 4]);
        qf[ks][3] = __float_as_uint(Ps[(m0 + gid + 8) * KPAD + ks * 8 + tig + 4]);
    }
    __syncthreads();

    float o[8][4];
#pragma unroll
    for (int a = 0; a < 8; a++)
#pragma unroll
        for (int e = 0; e < 4; e++) o[a][e] = 0.f;
    float l0 = 0.f, l1 = 0.f;

    // prologue: load tile 0 into buf 0
    {
#pragma unroll
        for (int i = 0; i < 4; i++) {
            int idx = tid + i * 256;
            int r = idx >> 4, j = (idx & 15) * 4;
            const float* src = QKV + (tokbase + r) * QKV_STR;
            cp_async16(ksb + (uint32_t)((r * KPAD + j) * 4), src + koff + j);
            cp_async16(vsb + (uint32_t)((r * VPAD + j) * 4), src + voff + j);
        }
        if (tid < 16) cp_async16(msb + tid * 16, mask + b * SEQ + tid * 4);
        asm volatile("cp.async.commit_group;" ::: "memory");
    }

    const int NT = SEQ / 64;
    for (int kt = 0; kt < NT; kt++) {
        const int buf = kt & 1;
        if (kt + 1 < NT) {
            const int nb = buf ^ 1;
            const int t0 = (kt + 1) * 64;
#pragma unroll
            for (int i = 0; i < 4; i++) {
                int idx = tid + i * 256;
                int r = idx >> 4, j = (idx & 15) * 4;
                const float* src = QKV + (tokbase + t0 + r) * QKV_STR;
                cp_async16(ksb + (uint32_t)((nb * KS_F + r * KPAD + j) * 4), src + koff + j);
                cp_async16(vsb + (uint32_t)((nb * VS_F + r * VPAD + j) * 4), src + voff + j);
            }
            if (tid < 16) cp_async16(msb + nb * 256 + tid * 16, mask + b * SEQ + t0 + tid * 4);
            asm volatile("cp.async.commit_group;" ::: "memory");
            asm volatile("cp.async.wait_group 1;" ::: "memory");
        } else {
            asm volatile("cp.async.wait_group 0;" ::: "memory");
        }
        __syncthreads();

        const float* ks_ = Ks + buf * KS_F;
        const float* vs_ = Vs + buf * VS_F;
        const int*   ms_ = Ms + buf * 64;

        // S = Q K^T, then P = exp(S) into Ps
#pragma unroll
        for (int at = 0; at < 8; at++) {
            float s[4] = {0.f, 0.f, 0.f, 0.f};
#pragma unroll
            for (int ks = 0; ks < 8; ks++) {
                uint32_t bf[2];
                bf[0] = __float_as_uint(ks_[(at * 8 + gid) * KPAD + ks * 8 + tig]);
                bf[1] = __float_as_uint(ks_[(at * 8 + gid) * KPAD + ks * 8 + tig + 4]);
                mma_tf32(s, qf[ks], bf);
            }
            const int c0 = at * 8 + 2 * tig;
            const int mk0 = ms_[c0], mk1 = ms_[c0 + 1];
            float p0 = mk0 ? rna_tf32(__expf(s[0])) : 0.f;
            float p1 = mk1 ? rna_tf32(__expf(s[1])) : 0.f;
            float p2 = mk0 ? rna_tf32(__expf(s[2])) : 0.f;
            float p3 = mk1 ? rna_tf32(__expf(s[3])) : 0.f;
            l0 += p0 + p1;
            l1 += p2 + p3;
            *(float2*)(Ps + (m0 + gid)     * KPAD + c0) = make_float2(p0, p1);
            *(float2*)(Ps + (m0 + gid + 8) * KPAD + c0) = make_float2(p2, p3);
        }
        __syncwarp();

        // O += P V
#pragma unroll
        for (int ks = 0; ks < 8; ks++) {
            uint32_t af[4];
            af[0] = __float_as_uint(Ps[(m0 + gid)     * KPAD + ks * 8 + tig]);
            af[1] = __float_as_uint(Ps[(m0 + gid + 8) * KPAD + ks * 8 + tig]);
            af[2] = __float_as_uint(Ps[(m0 + gid)     * KPAD + ks * 8 + tig + 4]);
            af[3] = __float_as_uint(Ps[(m0 + gid + 8) * KPAD + ks * 8 + tig + 4]);
#pragma unroll
            for (int at = 0; at < 8; at++) {
                uint32_t bf[2];
                bf[0] = __float_as_uint(vs_[(ks * 8 + tig)     * VPAD + at * 8 + gid]);
                bf[1] = __float_as_uint(vs_[(ks * 8 + tig + 4) * VPAD + at * 8 + gid]);
                mma_tf32(o[at], af, bf);
            }
        }
        __syncthreads();   // all warps done with this buf before it is reloaded
    }

    // row sums across quad
    l0 += __shfl_xor_sync(0xffffffffu, l0, 1);
    l0 += __shfl_xor_sync(0xffffffffu, l0, 2);
    l1 += __shfl_xor_sync(0xffffffffu, l1, 1);
    l1 += __shfl_xor_sync(0xffffffffu, l1, 2);
    const float inv0 = 1.0f / l0, inv1 = 1.0f / l1;

    float* o0 = O + (tokbase + q0 + m0 + gid)     * DMODEL + h * DK;
    float* o1 = O + (tokbase + q0 + m0 + gid + 8) * DMODEL + h * DK;
#pragma unroll
    for (int at = 0; at < 8; at++) {
        const int c = at * 8 + 2 * tig;
        *(float2*)(o0 + c) = make_float2(rna_tf32(o[at][0] * inv0),
                                         rna_tf32(o[at][1] * inv0));
        *(float2*)(o1 + c) = make_float2(rna_tf32(o[at][2] * inv1),
                                         rna_tf32(o[at][3] * inv1));
    }
}

// ---------------- launcher ---------------------------------------------------
extern "C" void kernel_launch(void* const* d_in, const int* in_sizes, int n_in,
                              void* d_out, int out_size)
{
    const float* x     = (const float*)d_in[0];
    const int*   mask  = (const int*)  d_in[1];
    const float* Wq    = (const float*)d_in[2];
    const float* bq    = (const float*)d_in[3];
    const float* Wk    = (const float*)d_in[4];
    const float* bk    = (const float*)d_in[5];
    const float* Wv    = (const float*)d_in[6];
    const float* bv    = (const float*)d_in[7];
    const float* Wo    = (const float*)d_in[8];
    const float* bo    = (const float*)d_in[9];
    const float* W1    = (const float*)d_in[10];
    const float* b1    = (const float*)d_in[11];
    const float* W2    = (const float*)d_in[12];
    const float* b2    = (const float*)d_in[13];
    const float* ln1g  = (const float*)d_in[14];
    const float* ln1b  = (const float*)d_in[15];
    const float* ln2g  = (const float*)d_in[16];
    const float* ln2b  = (const float*)d_in[17];
    float* out = (float*)d_out;

    float *h, *qkv, *att, *x1, *h2, *ff1;
    float *wqkvt, *bqkv, *wot, *w1t, *w2t;
    cudaGetSymbolAddress((void**)&h,    g_h);
    cudaGetSymbolAddress((void**)&qkv,  g_qkv);
    cudaGetSymbolAddress((void**)&att,  g_att);
    cudaGetSymbolAddress((void**)&x1,   g_x1);
    cudaGetSymbolAddress((void**)&h2,   g_h2);
    cudaGetSymbolAddress((void**)&ff1,  g_ff1);
    cudaGetSymbolAddress((void**)&wqkvt,g_wqkvt);
    cudaGetSymbolAddress((void**)&bqkv, g_bqkv);
    cudaGetSymbolAddress((void**)&wot,  g_wot);
    cudaGetSymbolAddress((void**)&w1t,  g_w1t);
    cudaGetSymbolAddress((void**)&w2t,  g_w2t);

    const int SMEM_GEMM = 4 * STAGE_F * sizeof(float);   // 65536 B
    cudaFuncSetAttribute(gemm_mma<0>, cudaFuncAttributeMaxDynamicSharedMemorySize, SMEM_GEMM);
    cudaFuncSetAttribute(gemm_mma<1>, cudaFuncAttributeMaxDynamicSharedMemorySize, SMEM_GEMM);
    cudaFuncSetAttribute(gemm_mma<2>, cudaFuncAttributeMaxDynamicSharedMemorySize, SMEM_GEMM);
    cudaFuncSetAttribute(attn_mma,    cudaFuncAttributeMaxDynamicSharedMemorySize, ATT_SMEM);

    dim3 tpb(32, 8);
    // weight transposes (+tf32 rounding); q,k,v stacked along N
    tp_rna<<<dim3(DMODEL/32, DMODEL/32), tpb>>>(Wq, wqkvt,                 DMODEL, DMODEL);
    tp_rna<<<dim3(DMODEL/32, DMODEL/32), tpb>>>(Wk, wqkvt + DMODEL*DMODEL, DMODEL, DMODEL);
    tp_rna<<<dim3(DMODEL/32, DMODEL/32), tpb>>>(Wv, wqkvt + 2*DMODEL*DMODEL, DMODEL, DMODEL);
    tp_rna<<<dim3(DMODEL/32, DMODEL/32), tpb>>>(Wo, wot, DMODEL, DMODEL);
    tp_rna<<<dim3(DFF/32,    DMODEL/32), tpb>>>(W1, w1t, DMODEL, DFF);
    tp_rna<<<dim3(DMODEL/32, DFF/32),    tpb>>>(W2, w2t, DFF, DMODEL);
    bias_cat<<<QKV_STR/256, 256>>>(bq, bk, bv, bqkv);

    dim3 gD(DMODEL / 128, NTOK / 128);   // (8, 64)
    dim3 gQKV(QKV_STR / 128, NTOK / 128);// (24, 64)
    dim3 gF(DFF / 128,    NTOK / 128);   // (32, 64)

    // h = LN1(x)  (tf32-rounded)
    ln_kernel<<<NTOK, 256>>>(x, ln1g, ln1b, h);
    // fused QKV projection (tf32-rounded outputs: mma operands downstream)
    gemm_mma<0><<<gQKV, 256, SMEM_GEMM>>>(h, wqkvt, bqkv, nullptr, qkv, NTOK, QKV_STR, DMODEL);
    // attention (tensor core)
    attn_mma<<<dim3(SEQ / 128, BATCH * NHEADS), 256, ATT_SMEM>>>(qkv, mask, att);
    // x1 = x + att @ Wo + bo
    gemm_mma<2><<<gD, 256, SMEM_GEMM>>>(att, wot, bo, x, x1, NTOK, DMODEL, DMODEL);
    // h2 = LN2(x1)  (tf32-rounded)
    ln_kernel<<<NTOK, 256>>>(x1, ln2g, ln2b, h2);
    // ff1 = gelu(h2 @ W1 + b1)  (tf32-rounded)
    gemm_mma<1><<<gF, 256, SMEM_GEMM>>>(h2, w1t, b1, nullptr, ff1, NTOK, DFF, DMODEL);
    // out = x1 + ff1 @ W2 + b2
    gemm_mma<2><<<gD, 256, SMEM_GEMM>>>(ff1, w2t, b2, x1, out, NTOK, DMODEL, DFF);
}

// round 7
// speedup vs baseline: 7.4579x; 1.7634x over previous
#include <cuda_runtime.h>
#include <cuda_fp16.h>
#include <math.h>
#include <stdint.h>

#define BATCH 4
#define SEQ   2048
#define DMODEL 1024
#define NHEADS 16
#define DK    64
#define DFF   4096
#define NTOK  (BATCH*SEQ)          // 8192
#define QKV_STR 3072

// ---------------- scratch (device globals; no allocation allowed) ----------
__device__ __half g_h   [NTOK*DMODEL];
__device__ __half g_qkv [NTOK*QKV_STR];
__device__ __half g_att [NTOK*DMODEL];
__device__ float  g_x1  [NTOK*DMODEL];
__device__ __half g_h2  [NTOK*DMODEL];
__device__ __half g_ff1 [NTOK*DFF];
// transposed (K-major, fp16) weights
__device__ __half g_wqkvt[3*DMODEL*DMODEL];  // [N=3072, K=1024]
__device__ float  g_bqkv [QKV_STR];
__device__ __half g_wot[DMODEL*DMODEL];
__device__ __half g_w1t[DFF*DMODEL];
__device__ __half g_w2t[DMODEL*DFF];

// ---------------- helpers ----------------------------------------------------
__device__ __forceinline__ uint32_t smem_u32(const void* p) {
    uint32_t a;
    asm("{ .reg .u64 t; cvta.to.shared.u64 t, %1; cvt.u32.u64 %0, t; }"
        : "=r"(a) : "l"(p));
    return a;
}
__device__ __forceinline__ void cp_async16(uint32_t dst, const void* src) {
    asm volatile("cp.async.cg.shared.global [%0], [%1], 16;" :: "r"(dst), "l"(src));
}

__device__ __forceinline__ void mma_f16(float (&d)[4], const uint32_t (&a)[4],
                                        const uint32_t (&b)[2]) {
    asm volatile("mma.sync.aligned.m16n8k16.row.col.f32.f16.f16.f32 "
        "{%0,%1,%2,%3}, {%4,%5,%6,%7}, {%8,%9}, {%0,%1,%2,%3};"
        : "+f"(d[0]), "+f"(d[1]), "+f"(d[2]), "+f"(d[3])
        : "r"(a[0]), "r"(a[1]), "r"(a[2]), "r"(a[3]), "r"(b[0]), "r"(b[1]));
}
__device__ __forceinline__ void ldmx4t(uint32_t (&r)[4], uint32_t addr) {
    asm volatile("ldmatrix.sync.aligned.m8n8.x4.trans.shared.b16 "
        "{%0,%1,%2,%3}, [%4];"
        : "=r"(r[0]), "=r"(r[1]), "=r"(r[2]), "=r"(r[3]) : "r"(addr));
}

// ---------------- layernorm: one block per token row -> fp16 out ------------
__global__ __launch_bounds__(256) void ln_kernel(const float* __restrict__ x,
                                                 const float* __restrict__ g,
                                                 const float* __restrict__ b,
                                                 __half* __restrict__ y)
{
    const int row = blockIdx.x;
    const int tid = threadIdx.x;
    const float* xr = x + (size_t)row * DMODEL;
    float4 v = *(const float4*)(xr + tid * 4);
    float s  = v.x + v.y + v.z + v.w;
    float s2 = v.x*v.x + v.y*v.y + v.z*v.z + v.w*v.w;

    __shared__ float red[64], red2[64];
    for (int o = 16; o > 0; o >>= 1) {
        s  += __shfl_xor_sync(0xffffffffu, s,  o);
        s2 += __shfl_xor_sync(0xffffffffu, s2, o);
    }
    int wid = tid >> 5, lid = tid & 31;
    if (lid == 0) { red[wid] = s; red2[wid] = s2; }
    __syncthreads();
    if (wid == 0) {
        float a  = (lid < 8) ? red[lid]  : 0.f;
        float a2 = (lid < 8) ? red2[lid] : 0.f;
        for (int o = 4; o > 0; o >>= 1) {
            a  += __shfl_xor_sync(0xffffffffu, a,  o);
            a2 += __shfl_xor_sync(0xffffffffu, a2, o);
        }
        if (lid == 0) { red[0] = a; red2[0] = a2; }
    }
    __syncthreads();
    float mu  = red[0]  * (1.0f / DMODEL);
    float var = red2[0] * (1.0f / DMODEL) - mu * mu;
    float rstd = rsqrtf(var + 1e-5f);

    int c = tid * 4;
    float4 gg = *(const float4*)(g + c);
    float4 bb = *(const float4*)(b + c);
    __half2 h01 = __floats2half2_rn((v.x - mu) * rstd * gg.x + bb.x,
                                    (v.y - mu) * rstd * gg.y + bb.y);
    __half2 h23 = __floats2half2_rn((v.z - mu) * rstd * gg.z + bb.z,
                                    (v.w - mu) * rstd * gg.w + bb.w);
    uint2 u;
    u.x = *(uint32_t*)&h01; u.y = *(uint32_t*)&h23;
    *(uint2*)(y + (size_t)row * DMODEL + c) = u;
}

// ---------------- weight transpose -> fp16: Wt[n,k] = h(W[k,n]) -------------
__global__ __launch_bounds__(256) void tp_h(const float* __restrict__ W,
                                            __half* __restrict__ Wt, int K, int N)
{
    __shared__ float t[32][33];
    int n0 = blockIdx.x * 32, k0 = blockIdx.y * 32;
    int tx = threadIdx.x, ty = threadIdx.y;  // 32 x 8
#pragma unroll
    for (int i = 0; i < 4; i++)
        t[ty + i*8][tx] = W[(size_t)(k0 + ty + i*8) * N + n0 + tx];
    __syncthreads();
#pragma unroll
    for (int i = 0; i < 4; i++)
        Wt[(size_t)(n0 + ty + i*8) * K + k0 + tx] = __float2half_rn(t[tx][ty + i*8]);
}

__global__ void bias_cat(const float* bq, const float* bk, const float* bv,
                         float* o)
{
    int i = blockIdx.x * 256 + threadIdx.x;
    o[i] = (i < DMODEL) ? bq[i] : (i < 2*DMODEL) ? bk[i - DMODEL] : bv[i - 2*DMODEL];
}

// ---------------- fp16 mma.sync GEMM: C = A[M,K] @ Bt[N,K]^T + epilogue -----
// 128x128 tile, BK=64, 256 threads (8 warps, warp tile 64x32), 2-stage cp.async.
// Smem half tiles stride 72 (conflict-free stores + fragment gathers).
// EPI: 0 = bias -> half, 1 = bias+gelu -> half, 2 = bias+residual -> float
#define GST 72
#define GSTAGE_H (128*GST)     // halves per stage per operand

template<int EPI, typename TC>
__global__ __launch_bounds__(256, 2)
void gemm_mma(const __half* __restrict__ A, const __half* __restrict__ Bt,
              const float* __restrict__ bias, const float* __restrict__ res,
              TC* __restrict__ C, int M, int N, int K)
{
    extern __shared__ __half smh[];
    __half* As = smh;                    // [2][128][GST]
    __half* Bs = smh + 2 * GSTAGE_H;
    const int tid = threadIdx.x, lane = tid & 31, w = tid >> 5;
    const int wm = w & 1, wn = w >> 1;
    const int gid = lane >> 2, tig = lane & 3;
    const int row0 = blockIdx.y * 128, col0 = blockIdx.x * 128;

    const uint32_t asb = smem_u32(As), bsb = smem_u32(Bs);

    float acc[4][4][4];
#pragma unroll
    for (int i = 0; i < 4; i++)
#pragma unroll
        for (int j = 0; j < 4; j++)
#pragma unroll
            for (int e = 0; e < 4; e++) acc[i][j][e] = 0.f;

    const int NCH = K >> 6;
    {
#pragma unroll
        for (int it = 0; it < 4; it++) {
            int idx = tid + it * 256;      // 0..1023
            int r = idx >> 3, j = idx & 7;
            uint32_t d = (uint32_t)((r * GST + j * 8) * 2);
            cp_async16(asb + d, A  + (size_t)(row0 + r) * K + j * 8);
            cp_async16(bsb + d, Bt + (size_t)(col0 + r) * K + j * 8);
        }
        asm volatile("cp.async.commit_group;" ::: "memory");
    }

    for (int i = 0; i < NCH; i++) {
        const int buf = i & 1;
        if (i + 1 < NCH) {
            const int nb = buf ^ 1;
            const int kof = (i + 1) << 6;
#pragma unroll
            for (int it = 0; it < 4; it++) {
                int idx = tid + it * 256;
                int r = idx >> 3, j = idx & 7;
                uint32_t d = (uint32_t)((nb * GSTAGE_H + r * GST + j * 8) * 2);
                cp_async16(asb + d, A  + (size_t)(row0 + r) * K + kof + j * 8);
                cp_async16(bsb + d, Bt + (size_t)(col0 + r) * K + kof + j * 8);
            }
            asm volatile("cp.async.commit_group;" ::: "memory");
            asm volatile("cp.async.wait_group 1;" ::: "memory");
        } else {
            asm volatile("cp.async.wait_group 0;" ::: "memory");
        }
        __syncthreads();

        const __half* as = As + buf * GSTAGE_H;
        const __half* bs = Bs + buf * GSTAGE_H;
#pragma unroll
        for (int ks = 0; ks < 4; ks++) {
            const int k0 = ks * 16 + 2 * tig;
            uint32_t af[4][4], bf[4][2];
#pragma unroll
            for (int mt = 0; mt < 4; mt++) {
                int r = wm * 64 + mt * 16 + gid;
                af[mt][0] = *(const uint32_t*)&as[r * GST + k0];
                af[mt][1] = *(const uint32_t*)&as[(r + 8) * GST + k0];
                af[mt][2] = *(const uint32_t*)&as[r * GST + k0 + 8];
                af[mt][3] = *(const uint32_t*)&as[(r + 8) * GST + k0 + 8];
            }
#pragma unroll
            for (int nt = 0; nt < 4; nt++) {
                int n = wn * 32 + nt * 8 + gid;
                bf[nt][0] = *(const uint32_t*)&bs[n * GST + k0];
                bf[nt][1] = *(const uint32_t*)&bs[n * GST + k0 + 8];
            }
#pragma unroll
            for (int mt = 0; mt < 4; mt++)
#pragma unroll
                for (int nt = 0; nt < 4; nt++)
                    mma_f16(acc[mt][nt], af[mt], bf[nt]);
        }
        __syncthreads();
    }

#pragma unroll
    for (int mt = 0; mt < 4; mt++) {
        const int r0 = row0 + wm * 64 + mt * 16 + gid;
#pragma unroll
        for (int nt = 0; nt < 4; nt++) {
            const int c = col0 + wn * 32 + nt * 8 + 2 * tig;
            const float b0 = bias[c], b1 = bias[c + 1];
            float o00 = acc[mt][nt][0] + b0, o01 = acc[mt][nt][1] + b1;
            float o10 = acc[mt][nt][2] + b0, o11 = acc[mt][nt][3] + b1;
            if (EPI == 1) {
                o00 = 0.5f * o00 * (1.0f + erff(o00 * 0.70710678118654752f));
                o01 = 0.5f * o01 * (1.0f + erff(o01 * 0.70710678118654752f));
                o10 = 0.5f * o10 * (1.0f + erff(o10 * 0.70710678118654752f));
                o11 = 0.5f * o11 * (1.0f + erff(o11 * 0.70710678118654752f));
            } else if (EPI == 2) {
                const float* rp0 = res + (size_t)r0 * N + c;
                const float* rp1 = res + (size_t)(r0 + 8) * N + c;
                o00 += rp0[0]; o01 += rp0[1];
                o10 += rp1[0]; o11 += rp1[1];
            }
            if (EPI == 2) {
                *(float2*)((float*)C + (size_t)r0 * N + c)       = make_float2(o00, o01);
                *(float2*)((float*)C + (size_t)(r0 + 8) * N + c) = make_float2(o10, o11);
            } else {
                __half2 v0 = __floats2half2_rn(o00, o01);
                __half2 v1 = __floats2half2_rn(o10, o11);
                *(uint32_t*)((__half*)C + (size_t)r0 * N + c)       = *(uint32_t*)&v0;
                *(uint32_t*)((__half*)C + (size_t)(r0 + 8) * N + c) = *(uint32_t*)&v1;
            }
        }
    }
}

// ---------------- attention: fp16 mma.sync flash-style ----------------------
// block = (b,h) x 128 q-rows; 256 threads = 8 warps x 16 q-rows.
// K/V 64-token tiles double-buffered; V fragments via ldmatrix.x4.trans.
#define APAD 72
#define KS_H (64*APAD)          // halves
#define VS_H (64*APAD)
#define PS_H (128*APAD)
#define KS_B (KS_H*2)
#define VS_B (VS_H*2)
#define ATT_SMEM ((2*KS_H + 2*VS_H + PS_H)*2 + 2*64*4)   // 55808 B

__global__ __launch_bounds__(256, 2)
void attn_mma(const __half* __restrict__ QKV, const int* __restrict__ mask,
              __half* __restrict__ O)
{
    extern __shared__ __half sm[];
    __half* Ks = sm;
    __half* Vs = sm + 2 * KS_H;
    __half* Ps = Vs + 2 * VS_H;
    int*    Ms = (int*)(Ps + PS_H);

    const int tid = threadIdx.x, lane = tid & 31, w = tid >> 5;
    const int gid = lane >> 2, tig = lane & 3;
    const int b = blockIdx.y >> 4, h = blockIdx.y & 15;
    const int q0 = blockIdx.x * 128, m0 = w * 16;
    const size_t tokbase = (size_t)b * SEQ;
    const int qoff = h * DK, koff = DMODEL + h * DK, voff = 2 * DMODEL + h * DK;

    const uint32_t ksb = smem_u32(Ks), vsb = smem_u32(Vs), msb = smem_u32(Ms);

    // ---- stage Q (scaled by 1/8, exact in fp16) into Ps ----
    const __half2 qscale = __floats2half2_rn(0.125f, 0.125f);
#pragma unroll
    for (int it = 0; it < 4; it++) {
        int idx = tid + it * 256;             // 0..1023 chunks of 8 halves
        int r = idx >> 3, j = (idx & 7) * 8;
        uint4 t = *(const uint4*)(QKV + (tokbase + q0 + r) * QKV_STR + qoff + j);
        __half2* hp = (__half2*)&t;
#pragma unroll
        for (int e = 0; e < 4; e++) hp[e] = __hmul2(hp[e], qscale);
        *(uint4*)(Ps + r * APAD + j) = t;
    }
    __syncthreads();
    uint32_t qf[4][4];
#pragma unroll
    for (int ks = 0; ks < 4; ks++) {
        const int k0 = ks * 16 + 2 * tig;
        qf[ks][0] = *(uint32_t*)&Ps[(m0 + gid)     * APAD + k0];
        qf[ks][1] = *(uint32_t*)&Ps[(m0 + gid + 8) * APAD + k0];
        qf[ks][2] = *(uint32_t*)&Ps[(m0 + gid)     * APAD + k0 + 8];
        qf[ks][3] = *(uint32_t*)&Ps[(m0 + gid + 8) * APAD + k0 + 8];
    }
    __syncthreads();

    float o[8][4];
#pragma unroll
    for (int a = 0; a < 8; a++)
#pragma unroll
        for (int e = 0; e < 4; e++) o[a][e] = 0.f;
    float l0 = 0.f, l1 = 0.f;

    // prologue: load tile 0 into buf 0
    {
#pragma unroll
        for (int it = 0; it < 2; it++) {
            int idx = tid + it * 256;        // 0..511
            int r = idx >> 3, j = (idx & 7) * 8;
            const __half* src = QKV + (tokbase + r) * QKV_STR;
            cp_async16(ksb + (uint32_t)((r * APAD + j) * 2), src + koff + j);
            cp_async16(vsb + (uint32_t)((r * APAD + j) * 2), src + voff + j);
        }
        if (tid < 16) cp_async16(msb + tid * 16, mask + b * SEQ + tid * 4);
        asm volatile("cp.async.commit_group;" ::: "memory");
    }

    const int NT = SEQ / 64;
    for (int kt = 0; kt < NT; kt++) {
        const int buf = kt & 1;
        if (kt + 1 < NT) {
            const int nb = buf ^ 1;
            const int t0 = (kt + 1) * 64;
#pragma unroll
            for (int it = 0; it < 2; it++) {
                int idx = tid + it * 256;
                int r = idx >> 3, j = (idx & 7) * 8;
                const __half* src = QKV + (tokbase + t0 + r) * QKV_STR;
                cp_async16(ksb + (uint32_t)((nb * KS_H + r * APAD + j) * 2), src + koff + j);
                cp_async16(vsb + (uint32_t)((nb * VS_H + r * APAD + j) * 2), src + voff + j);
            }
            if (tid < 16) cp_async16(msb + nb * 256 + tid * 16, mask + b * SEQ + t0 + tid * 4);
            asm volatile("cp.async.commit_group;" ::: "memory");
            asm volatile("cp.async.wait_group 1;" ::: "memory");
        } else {
            asm volatile("cp.async.wait_group 0;" ::: "memory");
        }
        __syncthreads();

        const __half* ks_ = Ks + buf * KS_H;
        const int*    ms_ = Ms + buf * 64;
        const uint32_t vb = vsb + buf * VS_B;

        // S = Q K^T -> P = exp(S) into Ps
#pragma unroll
        for (int at = 0; at < 8; at++) {
            float s[4] = {0.f, 0.f, 0.f, 0.f};
#pragma unroll
            for (int ks = 0; ks < 4; ks++) {
                const int k0 = ks * 16 + 2 * tig;
                uint32_t bf[2];
                bf[0] = *(const uint32_t*)&ks_[(at * 8 + gid) * APAD + k0];
                bf[1] = *(const uint32_t*)&ks_[(at * 8 + gid) * APAD + k0 + 8];
                mma_f16(s, qf[ks], bf);
            }
            const int c0 = at * 8 + 2 * tig;
            const int mk0 = ms_[c0], mk1 = ms_[c0 + 1];
            float p0 = mk0 ? __expf(s[0]) : 0.f;
            float p1 = mk1 ? __expf(s[1]) : 0.f;
            float p2 = mk0 ? __expf(s[2]) : 0.f;
            float p3 = mk1 ? __expf(s[3]) : 0.f;
            __half2 ph01 = __floats2half2_rn(p0, p1);
            __half2 ph23 = __floats2half2_rn(p2, p3);
            l0 += __low2float(ph01) + __high2float(ph01);
            l1 += __low2float(ph23) + __high2float(ph23);
            *(uint32_t*)&Ps[(m0 + gid)     * APAD + c0] = *(uint32_t*)&ph01;
            *(uint32_t*)&Ps[(m0 + gid + 8) * APAD + c0] = *(uint32_t*)&ph23;
        }
        __syncwarp();

        // O += P V   (V fragments via ldmatrix.x4.trans on [token][d] tile)
#pragma unroll
        for (int ks = 0; ks < 4; ks++) {
            const int k0 = ks * 16;
            const int kc = k0 + 2 * tig;
            uint32_t af[4];
            af[0] = *(uint32_t*)&Ps[(m0 + gid)     * APAD + kc];
            af[1] = *(uint32_t*)&Ps[(m0 + gid + 8) * APAD + kc];
            af[2] = *(uint32_t*)&Ps[(m0 + gid)     * APAD + kc + 8];
            af[3] = *(uint32_t*)&Ps[(m0 + gid + 8) * APAD + kc + 8];
#pragma unroll
            for (int atp = 0; atp < 4; atp++) {
                const int n0 = atp * 16;
                uint32_t vr[4];
                uint32_t vaddr = vb + (uint32_t)(((k0 + (lane & 7) + ((lane >> 3) & 1) * 8) * APAD
                                                  + n0 + (lane >> 4) * 8) * 2);
                ldmx4t(vr, vaddr);
                uint32_t b0[2] = {vr[0], vr[1]};
                uint32_t b1[2] = {vr[2], vr[3]};
                mma_f16(o[2 * atp],     af, b0);
                mma_f16(o[2 * atp + 1], af, b1);
            }
        }
        __syncthreads();
    }

    // row sums across quad
    l0 += __shfl_xor_sync(0xffffffffu, l0, 1);
    l0 += __shfl_xor_sync(0xffffffffu, l0, 2);
    l1 += __shfl_xor_sync(0xffffffffu, l1, 1);
    l1 += __shfl_xor_sync(0xffffffffu, l1, 2);
    const float inv0 = 1.0f / l0, inv1 = 1.0f / l1;

    __half* o0 = O + (tokbase + q0 + m0 + gid)     * DMODEL + h * DK;
    __half* o1 = O + (tokbase + q0 + m0 + gid + 8) * DMODEL + h * DK;
#pragma unroll
    for (int at = 0; at < 8; at++) {
        const int c = at * 8 + 2 * tig;
        __half2 v0 = __floats2half2_rn(o[at][0] * inv0, o[at][1] * inv0);
        __half2 v1 = __floats2half2_rn(o[at][2] * inv1, o[at][3] * inv1);
        *(uint32_t*)(o0 + c) = *(uint32_t*)&v0;
        *(uint32_t*)(o1 + c) = *(uint32_t*)&v1;
    }
}

// ---------------- launcher ---------------------------------------------------
extern "C" void kernel_launch(void* const* d_in, const int* in_sizes, int n_in,
                              void* d_out, int out_size)
{
    const float* x     = (const float*)d_in[0];
    const int*   mask  = (const int*)  d_in[1];
    const float* Wq    = (const float*)d_in[2];
    const float* bq    = (const float*)d_in[3];
    const float* Wk    = (const float*)d_in[4];
    const float* bk    = (const float*)d_in[5];
    const float* Wv    = (const float*)d_in[6];
    const float* bv    = (const float*)d_in[7];
    const float* Wo    = (const float*)d_in[8];
    const float* bo    = (const float*)d_in[9];
    const float* W1    = (const float*)d_in[10];
    const float* b1    = (const float*)d_in[11];
    const float* W2    = (const float*)d_in[12];
    const float* b2    = (const float*)d_in[13];
    const float* ln1g  = (const float*)d_in[14];
    const float* ln1b  = (const float*)d_in[15];
    const float* ln2g  = (const float*)d_in[16];
    const float* ln2b  = (const float*)d_in[17];
    float* out = (float*)d_out;

    __half *h, *qkv, *att, *h2, *ff1, *wqkvt, *wot, *w1t, *w2t;
    float *x1, *bqkv;
    cudaGetSymbolAddress((void**)&h,    g_h);
    cudaGetSymbolAddress((void**)&qkv,  g_qkv);
    cudaGetSymbolAddress((void**)&att,  g_att);
    cudaGetSymbolAddress((void**)&x1,   g_x1);
    cudaGetSymbolAddress((void**)&h2,   g_h2);
    cudaGetSymbolAddress((void**)&ff1,  g_ff1);
    cudaGetSymbolAddress((void**)&wqkvt,g_wqkvt);
    cudaGetSymbolAddress((void**)&bqkv, g_bqkv);
    cudaGetSymbolAddress((void**)&wot,  g_wot);
    cudaGetSymbolAddress((void**)&w1t,  g_w1t);
    cudaGetSymbolAddress((void**)&w2t,  g_w2t);

    const int SMEM_GEMM = 4 * GSTAGE_H * 2;   // 73728 B
    cudaFuncSetAttribute((gemm_mma<0, __half>), cudaFuncAttributeMaxDynamicSharedMemorySize, SMEM_GEMM);
    cudaFuncSetAttribute((gemm_mma<1, __half>), cudaFuncAttributeMaxDynamicSharedMemorySize, SMEM_GEMM);
    cudaFuncSetAttribute((gemm_mma<2, float>),  cudaFuncAttributeMaxDynamicSharedMemorySize, SMEM_GEMM);
    cudaFuncSetAttribute(attn_mma, cudaFuncAttributeMaxDynamicSharedMemorySize, ATT_SMEM);

    dim3 tpb(32, 8);
    tp_h<<<dim3(DMODEL/32, DMODEL/32), tpb>>>(Wq, wqkvt,                   DMODEL, DMODEL);
    tp_h<<<dim3(DMODEL/32, DMODEL/32), tpb>>>(Wk, wqkvt + DMODEL*DMODEL,   DMODEL, DMODEL);
    tp_h<<<dim3(DMODEL/32, DMODEL/32), tpb>>>(Wv, wqkvt + 2*DMODEL*DMODEL, DMODEL, DMODEL);
    tp_h<<<dim3(DMODEL/32, DMODEL/32), tpb>>>(Wo, wot, DMODEL, DMODEL);
    tp_h<<<dim3(DFF/32,    DMODEL/32), tpb>>>(W1, w1t, DMODEL, DFF);
    tp_h<<<dim3(DMODEL/32, DFF/32),    tpb>>>(W2, w2t, DFF, DMODEL);
    bias_cat<<<QKV_STR/256, 256>>>(bq, bk, bv, bqkv);

    dim3 gD(DMODEL / 128, NTOK / 128);   // (8, 64)
    dim3 gQKV(QKV_STR / 128, NTOK / 128);// (24, 64)
    dim3 gF(DFF / 128,    NTOK / 128);   // (32, 64)

    // h = LN1(x) -> fp16
    ln_kernel<<<NTOK, 256>>>(x, ln1g, ln1b, h);
    // fused QKV projection -> fp16
    gemm_mma<0, __half><<<gQKV, 256, SMEM_GEMM>>>(h, wqkvt, bqkv, nullptr, qkv, NTOK, QKV_STR, DMODEL);
    // attention -> fp16
    attn_mma<<<dim3(SEQ / 128, BATCH * NHEADS), 256, ATT_SMEM>>>(qkv, mask, att);
    // x1 = x + att @ Wo + bo  (fp32)
    gemm_mma<2, float><<<gD, 256, SMEM_GEMM>>>(att, wot, bo, x, x1, NTOK, DMODEL, DMODEL);
    // h2 = LN2(x1) -> fp16
    ln_kernel<<<NTOK, 256>>>(x1, ln2g, ln2b, h2);
    // ff1 = gelu(h2 @ W1 + b1) -> fp16
    gemm_mma<1, __half><<<gF, 256, SMEM_GEMM>>>(h2, w1t, b1, nullptr, ff1, NTOK, DFF, DMODEL);
    // out = x1 + ff1 @ W2 + b2  (fp32)
    gemm_mma<2, float><<<gD, 256, SMEM_GEMM>>>(ff1, w2t, b2, x1, out, NTOK, DMODEL, DFF);
}